// round 9
// baseline (speedup 1.0000x reference)
#include <cuda_runtime.h>
#include <cuda_bf16.h>
#include <cstdint>
#include <cstddef>

// Problem constants
constexpr int PB = 8, PS = 1024, PD = 768, PH = 12, PHD = 64;
constexpr size_t QKV_ELEMS = (size_t)PB * PH * PS * PHD;        // 6,291,456
constexpr size_t OUT_ELEMS = (size_t)PB * PS * PD;              // 6,291,456
constexpr size_t XE = (size_t)PB * PS * PD;                     // per matrix
constexpr size_t WE = (size_t)PD * PD;                          // per matrix
constexpr size_t RELP_ELEMS = (size_t)PB * PS * PS;             // 8,388,608

// Scratch (no allocations allowed -> __device__ globals)
__device__ __nv_bfloat16 g_xhi[3 * XE];
__device__ __nv_bfloat16 g_xlo[3 * XE];
__device__ __nv_bfloat16 g_whi[3 * WE];
__device__ __nv_bfloat16 g_wlo[3 * WE];
__device__ __nv_bfloat16 g_qhi[QKV_ELEMS], g_qlo[QKV_ELEMS];
__device__ __nv_bfloat16 g_khi[QKV_ELEMS], g_klo[QKV_ELEMS];
__device__ __nv_bfloat16 g_vhi[QKV_ELEMS], g_vlo[QKV_ELEMS];
__device__ __nv_bfloat16 g_vthi[QKV_ELEMS], g_vtlo[QKV_ELEMS];   // [b][h][hd][s]
__device__ float g_relp[RELP_ELEMS];
__device__ int   g_mask_mode;   // 0 = uint8/bool, 1 = int32, 2 = float32

// ---------------------------------------------------------------------------
// Tensor-core helpers (portable sm_80+ path: ldmatrix + mma.sync bf16)
// ---------------------------------------------------------------------------
__device__ __forceinline__ uint32_t smem_to_u32(const void* p) {
    uint32_t a;
    asm("{ .reg .u64 t; cvta.to.shared.u64 t, %1; cvt.u32.u64 %0, t; }" : "=r"(a) : "l"(p));
    return a;
}
__device__ __forceinline__ void ldmx4(uint32_t* r, uint32_t addr) {
    asm volatile("ldmatrix.sync.aligned.m8n8.x4.shared.b16 {%0,%1,%2,%3}, [%4];"
        : "=r"(r[0]), "=r"(r[1]), "=r"(r[2]), "=r"(r[3]) : "r"(addr));
}
__device__ __forceinline__ void mma16816(float* c, const uint32_t* a, uint32_t b0, uint32_t b1) {
    asm volatile("mma.sync.aligned.m16n8k16.row.col.f32.bf16.bf16.f32 "
        "{%0,%1,%2,%3}, {%4,%5,%6,%7}, {%8,%9}, {%0,%1,%2,%3};"
        : "+f"(c[0]), "+f"(c[1]), "+f"(c[2]), "+f"(c[3])
        : "r"(a[0]), "r"(a[1]), "r"(a[2]), "r"(a[3]), "r"(b0), "r"(b1));
}
#define SWZ128(off) ((off) ^ (((off) >> 3) & 0x70))

// ---------------------------------------------------------------------------
// Mask dtype probe (deterministic)
// ---------------------------------------------------------------------------
__global__ void detect_mask_kernel(const void* __restrict__ mask) {
    __shared__ int sawFloat, sawOther;
    if (threadIdx.x == 0) { sawFloat = 0; sawOther = 0; }
    __syncthreads();
    const unsigned int* w = (const unsigned int*)mask;
    int lf = 0, lo = 0;
    for (int i = threadIdx.x; i < 2048; i += blockDim.x) {
        unsigned int x = w[i];
        if (x == 0x3F800000u) lf = 1;
        else if (x > 1u) lo = 1;
    }
    if (lf) atomicOr(&sawFloat, 1);
    if (lo) atomicOr(&sawOther, 1);
    __syncthreads();
    if (threadIdx.x == 0) g_mask_mode = sawFloat ? 2 : (sawOther ? 0 : 1);
}

__device__ __forceinline__ bool read_mask(const void* m, size_t idx, int mode) {
    if (mode == 0) return ((const unsigned char*)m)[idx] != 0;
    if (mode == 1) return ((const int*)m)[idx] != 0;
    return ((const float*)m)[idx] != 0.0f;
}

// ---------------------------------------------------------------------------
// Conversion kernels: fp32 -> (bf16 hi, bf16 lo) split
// ---------------------------------------------------------------------------
__global__ void conv_x_kernel(const float* __restrict__ q, const float* __restrict__ k,
                              const float* __restrict__ v) {
    const int z = blockIdx.y;
    const float* src = (z == 0) ? q : (z == 1) ? k : v;
    __nv_bfloat16* hi = g_xhi + (size_t)z * XE;
    __nv_bfloat16* lo = g_xlo + (size_t)z * XE;
    const size_t i2 = ((size_t)blockIdx.x * blockDim.x + threadIdx.x) * 2;
    if (i2 + 1 >= XE) return;
    const float2 s = *(const float2*)(src + i2);
    const __nv_bfloat16 h0 = __float2bfloat16_rn(s.x);
    const __nv_bfloat16 h1 = __float2bfloat16_rn(s.y);
    *(__nv_bfloat162*)(hi + i2) = __halves2bfloat162(h0, h1);
    *(__nv_bfloat162*)(lo + i2) = __floats2bfloat162_rn(
        s.x - __bfloat162float(h0), s.y - __bfloat162float(h1));
}

__global__ void conv_w_kernel(const float* __restrict__ wq, const float* __restrict__ wk,
                              const float* __restrict__ wv) {
    const int z = blockIdx.y;
    const float* src = (z == 0) ? wq : (z == 1) ? wk : wv;
    __nv_bfloat16* hi = g_whi + (size_t)z * WE;
    __nv_bfloat16* lo = g_wlo + (size_t)z * WE;
    const size_t i2 = ((size_t)blockIdx.x * blockDim.x + threadIdx.x) * 2;
    if (i2 + 1 >= WE) return;
    const float2 s = *(const float2*)(src + i2);
    const __nv_bfloat16 h0 = __float2bfloat16_rn(s.x);
    const __nv_bfloat16 h1 = __float2bfloat16_rn(s.y);
    *(__nv_bfloat162*)(hi + i2) = __halves2bfloat162(h0, h1);
    *(__nv_bfloat162*)(lo + i2) = __floats2bfloat162_rn(
        s.x - __bfloat162float(h0), s.y - __bfloat162float(h1));
}

// ---------------------------------------------------------------------------
// relp kernel: rel_attn = softmax(where(rel*mask==0, -1e4, rel*mask)) per row.
// ---------------------------------------------------------------------------
__global__ void relp_kernel(const float* __restrict__ rel, const void* __restrict__ mask) {
    const int lane = threadIdx.x & 31;
    const int warp = threadIdx.x >> 5;
    const int row = blockIdx.x * 8 + warp;          // 0..8191 = b*1024+s
    const size_t rbase = (size_t)row * PS;
    const int mmode = g_mask_mode;
    float vals[32];
    float mx = -3.0e38f;
#pragma unroll
    for (int i = 0; i < 32; i++) {
        const int c = lane + i * 32;
        const bool m = read_mask(mask, rbase + c, mmode);
        const float v = rel[rbase + c];
        const float relm = m ? v : 0.0f;
        const float logit = (relm == 0.0f) ? -10000.0f : relm;
        vals[i] = logit;
        mx = fmaxf(mx, logit);
    }
#pragma unroll
    for (int o = 16; o; o >>= 1) mx = fmaxf(mx, __shfl_xor_sync(0xffffffffu, mx, o));
    float sum = 0.0f;
#pragma unroll
    for (int i = 0; i < 32; i++) { vals[i] = __expf(vals[i] - mx); sum += vals[i]; }
#pragma unroll
    for (int o = 16; o; o >>= 1) sum += __shfl_xor_sync(0xffffffffu, sum, o);
    const float inv = 1.0f / sum;
#pragma unroll
    for (int i = 0; i < 32; i++) g_relp[rbase + lane + i * 32] = vals[i] * inv;
}

// ---------------------------------------------------------------------------
// Kernel 1: HMMA bf16-split projection GEMM (emits bf16 hi/lo QKV).
// ---------------------------------------------------------------------------
constexpr int PROJ_SMEM = 4 * 16384;   // 64KB dynamic

__device__ __forceinline__ void load_slab_part(const __nv_bfloat16* __restrict__ src,
                                               int row0, int k0, char* dst, int tid) {
#pragma unroll
    for (int it = 0; it < 4; it++) {
        const int c = tid + it * 256;          // 0..1023 16B-chunks
        const int r = c >> 3;                  // 0..127
        const int e8 = (c & 7) * 8;            // bf16 element offset in row
        const uint4 v = *(const uint4*)(src + (size_t)(row0 + r) * PD + k0 + e8);
        *(uint4*)(dst + SWZ128(r * 128 + e8 * 2)) = v;
    }
}

__global__ __launch_bounds__(256, 2)
void proj_mma_kernel(const float* __restrict__ bq, const float* __restrict__ bk,
                     const float* __restrict__ bv)
{
    extern __shared__ char sm[];
    __shared__ float bias_s[128];

    const int tid  = threadIdx.x;
    const int warp = tid >> 5;
    const int lane = tid & 31;
    const int wm = warp >> 2;
    const int wn = warp & 3;
    const int z  = blockIdx.z;
    const int n0 = blockIdx.x * 128;
    const int m0 = blockIdx.y * 128;

    const __nv_bfloat16* xhi = g_xhi + (size_t)z * XE;
    const __nv_bfloat16* xlo = g_xlo + (size_t)z * XE;
    const __nv_bfloat16* whi = g_whi + (size_t)z * WE;
    const __nv_bfloat16* wlo = g_wlo + (size_t)z * WE;
    const float* bias = (z == 0) ? bq : (z == 1) ? bk : bv;
    __nv_bfloat16* ohi = (z == 0) ? g_qhi : (z == 1) ? g_khi : g_vhi;
    __nv_bfloat16* olo = (z == 0) ? g_qlo : (z == 1) ? g_klo : g_vlo;

    if (tid < 128) bias_s[tid] = bias[n0 + tid];

    char* Ahi_s = sm;
    char* Alo_s = sm + 16384;
    char* Bhi_s = sm + 32768;
    char* Blo_s = sm + 49152;
    const uint32_t uAhi = smem_to_u32(Ahi_s);
    const uint32_t uAlo = smem_to_u32(Alo_s);
    const uint32_t uBhi = smem_to_u32(Bhi_s);
    const uint32_t uBlo = smem_to_u32(Blo_s);

    float acc[4][4][4];
#pragma unroll
    for (int i = 0; i < 4; i++)
#pragma unroll
        for (int j = 0; j < 4; j++)
#pragma unroll
            for (int c = 0; c < 4; c++) acc[i][j][c] = 0.0f;

    const int lrow  = lane & 15;
    const int lcolb = (lane >> 4) * 16;

    for (int s = 0; s < 12; s++) {
        __syncthreads();
        const int k0 = s * 64;
        load_slab_part(xhi, m0, k0, Ahi_s, tid);
        load_slab_part(xlo, m0, k0, Alo_s, tid);
        load_slab_part(whi, n0, k0, Bhi_s, tid);
        load_slab_part(wlo, n0, k0, Blo_s, tid);
        __syncthreads();
#pragma unroll
        for (int ks = 0; ks < 4; ks++) {
            const int kb = ks * 32 + lcolb;
            uint32_t bhi[2][4], blo[2][4];
#pragma unroll
            for (int nt2 = 0; nt2 < 2; nt2++) {
                const int brow = wn * 32 + nt2 * 16 + lrow;
                ldmx4(bhi[nt2], uBhi + SWZ128(brow * 128 + kb));
                ldmx4(blo[nt2], uBlo + SWZ128(brow * 128 + kb));
            }
#pragma unroll
            for (int mt = 0; mt < 4; mt++) {
                const int arow = wm * 64 + mt * 16 + lrow;
                uint32_t a[4];
                ldmx4(a, uAhi + SWZ128(arow * 128 + kb));       // Ahi
#pragma unroll
                for (int nt2 = 0; nt2 < 2; nt2++)
#pragma unroll
                    for (int j = 0; j < 2; j++) {
                        mma16816(acc[mt][nt2 * 2 + j], a, bhi[nt2][j], bhi[nt2][2 + j]);
                        mma16816(acc[mt][nt2 * 2 + j], a, blo[nt2][j], blo[nt2][2 + j]);
                    }
                ldmx4(a, uAlo + SWZ128(arow * 128 + kb));       // Alo
#pragma unroll
                for (int nt2 = 0; nt2 < 2; nt2++)
#pragma unroll
                    for (int j = 0; j < 2; j++)
                        mma16816(acc[mt][nt2 * 2 + j], a, bhi[nt2][j], bhi[nt2][2 + j]);
            }
        }
    }

    // Epilogue: +bias, split to bf16 hi/lo, scatter [b][h][s][hd]
    const int g   = lane >> 2;
    const int tg2 = (lane & 3) * 2;
#pragma unroll
    for (int mt = 0; mt < 4; mt++) {
#pragma unroll
        for (int nt = 0; nt < 4; nt++) {
            const int nc = wn * 32 + nt * 8 + tg2;
            const int n = n0 + nc;
            const int h = n >> 6, hd = n & 63;
            const int m = m0 + wm * 64 + mt * 16 + g;
            const int b = m >> 10, sq = m & 1023;
#pragma unroll
            for (int cc = 0; cc < 2; cc++) {
                const float y0 = acc[mt][nt][cc * 2 + 0] + bias_s[nc];
                const float y1 = acc[mt][nt][cc * 2 + 1] + bias_s[nc + 1];
                const __nv_bfloat16 h0 = __float2bfloat16_rn(y0);
                const __nv_bfloat16 h1 = __float2bfloat16_rn(y1);
                const size_t di = (((size_t)(b * PH + h)) * PS + sq + cc * 8) * PHD + hd;
                *(__nv_bfloat162*)(ohi + di) = __halves2bfloat162(h0, h1);
                *(__nv_bfloat162*)(olo + di) = __floats2bfloat162_rn(
                    y0 - __bfloat162float(h0), y1 - __bfloat162float(h1));
            }
        }
    }
}

// ---------------------------------------------------------------------------
// V transpose: [b][h][s][hd] -> [b][h][hd][s] (hi and lo)
// ---------------------------------------------------------------------------
__global__ void vtrans_kernel() {
    __shared__ __nv_bfloat16 th[64][65], tl[64][65];
    const int tid = threadIdx.x;
    const int bh = blockIdx.y;
    const int st = blockIdx.x * 64;
    const size_t src0 = ((size_t)bh * PS + st) * PHD;
#pragma unroll
    for (int it = 0; it < 16; it++) {
        const int i = tid + it * 256;
        const int s = i >> 6, hd = i & 63;
        th[hd][s] = g_vhi[src0 + (size_t)s * PHD + hd];
        tl[hd][s] = g_vlo[src0 + (size_t)s * PHD + hd];
    }
    __syncthreads();
    const size_t dst0 = (size_t)bh * PHD * PS + st;
#pragma unroll
    for (int it = 0; it < 16; it++) {
        const int i = tid + it * 256;
        const int hd = i >> 6, s = i & 63;
        g_vthi[dst0 + (size_t)hd * PS + s] = th[hd][s];
        g_vtlo[dst0 + (size_t)hd * PS + s] = tl[hd][s];
    }
}

// ---------------------------------------------------------------------------
// Kernel 2 (FUSED): per CTA (b,h, 32 q-rows):
//   QK^T/8 masked -> sbuf, softmax+combine -> prob (gmem) AND sbuf in place,
//   then PV: out = prob @ V using sbuf slabs converted to bf16 hi/lo.
// smem: sbuf f32[32][1028] @0 (131584), qhi@131584(4096), qlo@135680(4096),
//       kbuf@139776(32768: QK-phase khi/klo; PV-phase phi/plo/vhi/vlo),
//       msk@172544(32768) = 205312
// ---------------------------------------------------------------------------
constexpr int SC_SMEM = 205312;
constexpr int SC_QHI = 131584, SC_QLO = 135680, SC_KBUF = 139776, SC_MSK = 172544;

__global__ __launch_bounds__(256, 1)
void attn_fused_kernel(const void* __restrict__ mask, const float* __restrict__ l1p,
                       float* __restrict__ prob, float* __restrict__ outp)
{
    extern __shared__ char sm2[];
    float* sbuf = (float*)sm2;
    char* qhi_s = sm2 + SC_QHI;
    char* qlo_s = sm2 + SC_QLO;
    char* khi_s = sm2 + SC_KBUF;
    char* klo_s = sm2 + SC_KBUF + 16384;
    unsigned char* msk = (unsigned char*)(sm2 + SC_MSK);
    const uint32_t uQhi = smem_to_u32(qhi_s);
    const uint32_t uQlo = smem_to_u32(qlo_s);
    const uint32_t uKhi = smem_to_u32(khi_s);
    const uint32_t uKlo = smem_to_u32(klo_s);
    // PV-phase overlay of the K region
    char* phi_s = khi_s;                 // 4096  (32 q x 64 k bf16)
    char* plo_s = khi_s + 4096;          // 4096
    char* vhi_s = khi_s + 8192;          // 8192  (64 hd x 64 s bf16)
    char* vlo_s = khi_s + 16384;         // 8192
    const uint32_t uPhi = smem_to_u32(phi_s);
    const uint32_t uPlo = smem_to_u32(plo_s);
    const uint32_t uVhi = smem_to_u32(vhi_s);
    const uint32_t uVlo = smem_to_u32(vlo_s);

    const int tid  = threadIdx.x;
    const int warp = tid >> 5;
    const int lane = tid & 31;
    const int wm = warp >> 2;          // 0..1 (16 rows)
    const int wn = warp & 3;           // 0..3 (32 cols)
    const int bh = blockIdx.y;
    const int b = bh / PH, h = bh % PH;
    const int q0 = blockIdx.x * 32;
    const int mmode = g_mask_mode;
    const float l1 = *l1p;
    const float w0 = 1.0f - l1;

    // mask tile -> smem bytes
    const size_t mrow = ((size_t)b * PS + q0) * PS;
    for (int i = tid; i < 32 * 1024; i += 256)
        msk[i] = read_mask(mask, mrow + i, mmode) ? 1 : 0;

    // Q tile (32 x 64), hi+lo
    {
        const size_t qoff = ((size_t)bh * PS + q0) * PHD;
        const int r = tid >> 3, e8 = (tid & 7) * 8;
        *(uint4*)(qhi_s + SWZ128(r * 128 + e8 * 2)) =
            *(const uint4*)(g_qhi + qoff + (size_t)r * PHD + e8);
        *(uint4*)(qlo_s + SWZ128(r * 128 + e8 * 2)) =
            *(const uint4*)(g_qlo + qoff + (size_t)r * PHD + e8);
    }

    const int lrow  = lane & 15;
    const int lcolb = (lane >> 4) * 16;
    const int g   = lane >> 2;
    const int tg2 = (lane & 3) * 2;
    const size_t kbh = (size_t)bh * PS * PHD;

    // ---------------- QK phase ----------------
    for (int kc0 = 0; kc0 < PS; kc0 += 128) {
        __syncthreads();
#pragma unroll
        for (int it = 0; it < 4; it++) {
            const int c = tid + it * 256;
            const int r = c >> 3, e8 = (c & 7) * 8;
            *(uint4*)(khi_s + SWZ128(r * 128 + e8 * 2)) =
                *(const uint4*)(g_khi + kbh + (size_t)(kc0 + r) * PHD + e8);
            *(uint4*)(klo_s + SWZ128(r * 128 + e8 * 2)) =
                *(const uint4*)(g_klo + kbh + (size_t)(kc0 + r) * PHD + e8);
        }
        __syncthreads();

        float acc[4][4];
#pragma unroll
        for (int i = 0; i < 4; i++)
#pragma unroll
            for (int c = 0; c < 4; c++) acc[i][c] = 0.0f;
#pragma unroll
        for (int ks = 0; ks < 4; ks++) {
            const int kb = ks * 32 + lcolb;
            uint32_t bhi[2][4], blo[2][4], ahi[4], alo[4];
#pragma unroll
            for (int nt2 = 0; nt2 < 2; nt2++) {
                const int brow = wn * 32 + nt2 * 16 + lrow;
                ldmx4(bhi[nt2], uKhi + SWZ128(brow * 128 + kb));
                ldmx4(blo[nt2], uKlo + SWZ128(brow * 128 + kb));
            }
            const int arow = wm * 16 + lrow;
            ldmx4(ahi, uQhi + SWZ128(arow * 128 + kb));
            ldmx4(alo, uQlo + SWZ128(arow * 128 + kb));
#pragma unroll
            for (int nt2 = 0; nt2 < 2; nt2++)
#pragma unroll
                for (int j = 0; j < 2; j++) {
                    mma16816(acc[nt2 * 2 + j], ahi, bhi[nt2][j], bhi[nt2][2 + j]);
                    mma16816(acc[nt2 * 2 + j], ahi, blo[nt2][j], blo[nt2][2 + j]);
                    mma16816(acc[nt2 * 2 + j], alo, bhi[nt2][j], bhi[nt2][2 + j]);
                }
        }
        const int r0 = wm * 16 + g, r1 = r0 + 8;
#pragma unroll
        for (int nt = 0; nt < 4; nt++) {
            const int kcol = kc0 + wn * 32 + nt * 8 + tg2;
            const int mi0 = r0 * 1024 + kcol, mi1 = r1 * 1024 + kcol;
            sbuf[r0 * 1028 + kcol]     = msk[mi0]     ? -1.0e9f : acc[nt][0] * 0.125f;
            sbuf[r0 * 1028 + kcol + 1] = msk[mi0 + 1] ? -1.0e9f : acc[nt][1] * 0.125f;
            sbuf[r1 * 1028 + kcol]     = msk[mi1]     ? -1.0e9f : acc[nt][2] * 0.125f;
            sbuf[r1 * 1028 + kcol + 1] = msk[mi1 + 1] ? -1.0e9f : acc[nt][3] * 0.125f;
        }
    }
    __syncthreads();

    // ---------------- softmax + combine; write prob (gmem) AND sbuf ----------------
#pragma unroll
    for (int rr = 0; rr < 4; rr++) {
        const int r = warp * 4 + rr;
        float vals[32];
        float mx = -3.0e38f;
#pragma unroll
        for (int i = 0; i < 32; i++) {
            vals[i] = sbuf[r * 1028 + lane + i * 32];
            mx = fmaxf(mx, vals[i]);
        }
#pragma unroll
        for (int o = 16; o; o >>= 1) mx = fmaxf(mx, __shfl_xor_sync(0xffffffffu, mx, o));
        float sum = 0.0f;
#pragma unroll
        for (int i = 0; i < 32; i++) { vals[i] = __expf(vals[i] - mx); sum += vals[i]; }
#pragma unroll
        for (int o = 16; o; o >>= 1) sum += __shfl_xor_sync(0xffffffffu, sum, o);
        const float inv = 1.0f / sum;
        const size_t pb = (((size_t)(b * PH + h)) * PS + q0 + r) * PS;
        const float* rp = g_relp + ((size_t)b * PS + q0 + r) * PS;
#pragma unroll
        for (int i = 0; i < 32; i++) {
            const int c = lane + i * 32;
            const float p = w0 * vals[i] * inv + l1 * rp[c];
            prob[pb + c] = p;
            sbuf[r * 1028 + c] = p;             // in place: row owned by this warp
        }
    }

    // ---------------- PV phase: out[32q x 64hd] = sbuf(prob) @ V ----------------
    // warp tile: wm2 (0..1) x 16 q-rows, wn (0..3) x 16 hd-cols
    float pacc[2][4];
#pragma unroll
    for (int j = 0; j < 2; j++)
#pragma unroll
        for (int c = 0; c < 4; c++) pacc[j][c] = 0.0f;

    const size_t vtb = (size_t)bh * PHD * PS;

    for (int kc0 = 0; kc0 < PS; kc0 += 64) {
        __syncthreads();
        // convert prob slab [32 q][64 k] fp32 -> bf16 hi/lo swizzled tiles
        {
            const int i8 = tid * 8;                 // 2048 elements / 256 threads
            const int r = i8 >> 6, c0 = i8 & 63;
            const float* srcp = sbuf + r * 1028 + kc0 + c0;
            float v[8];
            *(float4*)&v[0] = *(const float4*)(srcp);
            *(float4*)&v[4] = *(const float4*)(srcp + 4);
            __nv_bfloat16 hh[8];
            __nv_bfloat16 ll[8];
#pragma unroll
            for (int e = 0; e < 8; e++) {
                hh[e] = __float2bfloat16_rn(v[e]);
                ll[e] = __float2bfloat16_rn(v[e] - __bfloat162float(hh[e]));
            }
            *(uint4*)(phi_s + SWZ128(r * 128 + c0 * 2)) = *(const uint4*)hh;
            *(uint4*)(plo_s + SWZ128(r * 128 + c0 * 2)) = *(const uint4*)ll;
        }
        // V^T slab [64 hd][64 s] hi/lo
#pragma unroll
        for (int it = 0; it < 2; it++) {
            const int c = tid + it * 256;          // 0..511 16B chunks
            const int r = c >> 3, e8 = (c & 7) * 8;
            *(uint4*)(vhi_s + SWZ128(r * 128 + e8 * 2)) =
                *(const uint4*)(g_vthi + vtb + (size_t)r * PS + kc0 + e8);
            *(uint4*)(vlo_s + SWZ128(r * 128 + e8 * 2)) =
                *(const uint4*)(g_vtlo + vtb + (size_t)r * PS + kc0 + e8);
        }
        __syncthreads();
#pragma unroll
        for (int ks = 0; ks < 4; ks++) {
            const int kb = ks * 32 + lcolb;
            uint32_t bhi[4], blo[4], ahi[4], alo[4];
            const int brow = wn * 16 + lrow;          // hd rows for this warp
            ldmx4(bhi, uVhi + SWZ128(brow * 128 + kb));
            ldmx4(blo, uVlo + SWZ128(brow * 128 + kb));
            const int arow = wm * 16 + lrow;          // q rows for this warp
            ldmx4(ahi, uPhi + SWZ128(arow * 128 + kb));
            ldmx4(alo, uPlo + SWZ128(arow * 128 + kb));
#pragma unroll
            for (int j = 0; j < 2; j++) {
                mma16816(pacc[j], ahi, bhi[j], bhi[2 + j]);
                mma16816(pacc[j], ahi, blo[j], blo[2 + j]);
                mma16816(pacc[j], alo, bhi[j], bhi[2 + j]);
            }
        }
    }
    // epilogue: write out[b][sq][h*64+hd]
#pragma unroll
    for (int j = 0; j < 2; j++) {
        const int nc = wn * 16 + j * 8 + tg2;        // hd col
        const int m = q0 + wm * 16 + g;              // q row
        float2 v0, v1;
        v0.x = pacc[j][0]; v0.y = pacc[j][1];
        v1.x = pacc[j][2]; v1.y = pacc[j][3];
        *(float2*)(outp + ((size_t)b * PS + m) * PD + h * PHD + nc)     = v0;
        *(float2*)(outp + ((size_t)b * PS + m + 8) * PD + h * PHD + nc) = v1;
    }
}

// ---------------------------------------------------------------------------
extern "C" void kernel_launch(void* const* d_in, const int* in_sizes, int n_in,
                              void* d_out, int out_size) {
    const float* query = (const float*)d_in[0];
    const float* key   = (const float*)d_in[1];
    const float* value = (const float*)d_in[2];
    const float* rel   = (const float*)d_in[3];
    const void*  mask  = d_in[4];
    const float* l1    = (const float*)d_in[5];
    const float* Wq    = (const float*)d_in[6];
    const float* bq    = (const float*)d_in[7];
    const float* Wk    = (const float*)d_in[8];
    const float* bk    = (const float*)d_in[9];
    const float* Wv    = (const float*)d_in[10];
    const float* bv    = (const float*)d_in[11];

    float* outp = (float*)d_out;
    float* prob = outp + OUT_ELEMS;

    detect_mask_kernel<<<1, 256>>>(mask);

    conv_x_kernel<<<dim3((unsigned)(XE / 512), 3), 256>>>(query, key, value);
    conv_w_kernel<<<dim3((unsigned)(WE / 512), 3), 256>>>(Wq, Wk, Wv);
    relp_kernel<<<1024, 256>>>(rel, mask);

    cudaFuncSetAttribute(proj_mma_kernel,
                         cudaFuncAttributeMaxDynamicSharedMemorySize, PROJ_SMEM);
    dim3 g1(PD / 128, (PB * PS) / 128, 3);     // (6, 64, 3)
    proj_mma_kernel<<<g1, 256, PROJ_SMEM>>>(bq, bk, bv);

    vtrans_kernel<<<dim3(16, PB * PH), 256>>>();

    cudaFuncSetAttribute(attn_fused_kernel,
                         cudaFuncAttributeMaxDynamicSharedMemorySize, SC_SMEM);
    dim3 g2(PS / 32, PB * PH);                 // (32, 96)
    attn_fused_kernel<<<g2, 256, SC_SMEM>>>(mask, l1, prob, outp);
}

// round 10
// speedup vs baseline: 1.1482x; 1.1482x over previous
#include <cuda_runtime.h>
#include <cuda_bf16.h>
#include <cstdint>
#include <cstddef>

// Problem constants
constexpr int PB = 8, PS = 1024, PD = 768, PH = 12, PHD = 64;
constexpr size_t QKV_ELEMS = (size_t)PB * PH * PS * PHD;        // 6,291,456
constexpr size_t OUT_ELEMS = (size_t)PB * PS * PD;              // 6,291,456
constexpr size_t XE = (size_t)PB * PS * PD;                     // per matrix
constexpr size_t WE = (size_t)PD * PD;                          // per matrix
constexpr size_t RELP_ELEMS = (size_t)PB * PS * PS;             // 8,388,608

// Scratch (no allocations allowed -> __device__ globals)
__device__ __nv_bfloat16 g_xhi[3 * XE];
__device__ __nv_bfloat16 g_xlo[3 * XE];
__device__ __nv_bfloat16 g_whi[3 * WE];
__device__ __nv_bfloat16 g_wlo[3 * WE];
__device__ __nv_bfloat16 g_qhi[QKV_ELEMS], g_qlo[QKV_ELEMS];
__device__ __nv_bfloat16 g_khi[QKV_ELEMS], g_klo[QKV_ELEMS];
__device__ __nv_bfloat16 g_vhi[QKV_ELEMS], g_vlo[QKV_ELEMS];
__device__ __nv_bfloat16 g_vthi[QKV_ELEMS], g_vtlo[QKV_ELEMS];   // [b][h][hd][s]
__device__ float g_relp[RELP_ELEMS];
__device__ int   g_mask_mode;   // 0 = uint8/bool, 1 = int32, 2 = float32

// ---------------------------------------------------------------------------
// Tensor-core helpers (portable sm_80+ path: ldmatrix + mma.sync bf16)
// ---------------------------------------------------------------------------
__device__ __forceinline__ uint32_t smem_to_u32(const void* p) {
    uint32_t a;
    asm("{ .reg .u64 t; cvta.to.shared.u64 t, %1; cvt.u32.u64 %0, t; }" : "=r"(a) : "l"(p));
    return a;
}
__device__ __forceinline__ void ldmx4(uint32_t* r, uint32_t addr) {
    asm volatile("ldmatrix.sync.aligned.m8n8.x4.shared.b16 {%0,%1,%2,%3}, [%4];"
        : "=r"(r[0]), "=r"(r[1]), "=r"(r[2]), "=r"(r[3]) : "r"(addr));
}
__device__ __forceinline__ void mma16816(float* c, const uint32_t* a, uint32_t b0, uint32_t b1) {
    asm volatile("mma.sync.aligned.m16n8k16.row.col.f32.bf16.bf16.f32 "
        "{%0,%1,%2,%3}, {%4,%5,%6,%7}, {%8,%9}, {%0,%1,%2,%3};"
        : "+f"(c[0]), "+f"(c[1]), "+f"(c[2]), "+f"(c[3])
        : "r"(a[0]), "r"(a[1]), "r"(a[2]), "r"(a[3]), "r"(b0), "r"(b1));
}
#define SWZ128(off) ((off) ^ (((off) >> 3) & 0x70))

// ---------------------------------------------------------------------------
// Mask dtype probe (deterministic)
// ---------------------------------------------------------------------------
__global__ void detect_mask_kernel(const void* __restrict__ mask) {
    __shared__ int sawFloat, sawOther;
    if (threadIdx.x == 0) { sawFloat = 0; sawOther = 0; }
    __syncthreads();
    const unsigned int* w = (const unsigned int*)mask;
    int lf = 0, lo = 0;
    for (int i = threadIdx.x; i < 2048; i += blockDim.x) {
        unsigned int x = w[i];
        if (x == 0x3F800000u) lf = 1;
        else if (x > 1u) lo = 1;
    }
    if (lf) atomicOr(&sawFloat, 1);
    if (lo) atomicOr(&sawOther, 1);
    __syncthreads();
    if (threadIdx.x == 0) g_mask_mode = sawFloat ? 2 : (sawOther ? 0 : 1);
}

__device__ __forceinline__ bool read_mask(const void* m, size_t idx, int mode) {
    if (mode == 0) return ((const unsigned char*)m)[idx] != 0;
    if (mode == 1) return ((const int*)m)[idx] != 0;
    return ((const float*)m)[idx] != 0.0f;
}

// ---------------------------------------------------------------------------
// Conversion kernels: fp32 -> (bf16 hi, bf16 lo) split
// ---------------------------------------------------------------------------
__global__ void conv_x_kernel(const float* __restrict__ q, const float* __restrict__ k,
                              const float* __restrict__ v) {
    const int z = blockIdx.y;
    const float* src = (z == 0) ? q : (z == 1) ? k : v;
    __nv_bfloat16* hi = g_xhi + (size_t)z * XE;
    __nv_bfloat16* lo = g_xlo + (size_t)z * XE;
    const size_t i2 = ((size_t)blockIdx.x * blockDim.x + threadIdx.x) * 2;
    if (i2 + 1 >= XE) return;
    const float2 s = *(const float2*)(src + i2);
    const __nv_bfloat16 h0 = __float2bfloat16_rn(s.x);
    const __nv_bfloat16 h1 = __float2bfloat16_rn(s.y);
    *(__nv_bfloat162*)(hi + i2) = __halves2bfloat162(h0, h1);
    *(__nv_bfloat162*)(lo + i2) = __floats2bfloat162_rn(
        s.x - __bfloat162float(h0), s.y - __bfloat162float(h1));
}

__global__ void conv_w_kernel(const float* __restrict__ wq, const float* __restrict__ wk,
                              const float* __restrict__ wv) {
    const int z = blockIdx.y;
    const float* src = (z == 0) ? wq : (z == 1) ? wk : wv;
    __nv_bfloat16* hi = g_whi + (size_t)z * WE;
    __nv_bfloat16* lo = g_wlo + (size_t)z * WE;
    const size_t i2 = ((size_t)blockIdx.x * blockDim.x + threadIdx.x) * 2;
    if (i2 + 1 >= WE) return;
    const float2 s = *(const float2*)(src + i2);
    const __nv_bfloat16 h0 = __float2bfloat16_rn(s.x);
    const __nv_bfloat16 h1 = __float2bfloat16_rn(s.y);
    *(__nv_bfloat162*)(hi + i2) = __halves2bfloat162(h0, h1);
    *(__nv_bfloat162*)(lo + i2) = __floats2bfloat162_rn(
        s.x - __bfloat162float(h0), s.y - __bfloat162float(h1));
}

// ---------------------------------------------------------------------------
// relp kernel: rel_attn = softmax(where(rel*mask==0, -1e4, rel*mask)) per row.
// ---------------------------------------------------------------------------
__global__ void relp_kernel(const float* __restrict__ rel, const void* __restrict__ mask) {
    const int lane = threadIdx.x & 31;
    const int warp = threadIdx.x >> 5;
    const int row = blockIdx.x * 8 + warp;          // 0..8191 = b*1024+s
    const size_t rbase = (size_t)row * PS;
    const int mmode = g_mask_mode;
    float vals[32];
    float mx = -3.0e38f;
#pragma unroll
    for (int i = 0; i < 32; i++) {
        const int c = lane + i * 32;
        const bool m = read_mask(mask, rbase + c, mmode);
        const float v = rel[rbase + c];
        const float relm = m ? v : 0.0f;
        const float logit = (relm == 0.0f) ? -10000.0f : relm;
        vals[i] = logit;
        mx = fmaxf(mx, logit);
    }
#pragma unroll
    for (int o = 16; o; o >>= 1) mx = fmaxf(mx, __shfl_xor_sync(0xffffffffu, mx, o));
    float sum = 0.0f;
#pragma unroll
    for (int i = 0; i < 32; i++) { vals[i] = __expf(vals[i] - mx); sum += vals[i]; }
#pragma unroll
    for (int o = 16; o; o >>= 1) sum += __shfl_xor_sync(0xffffffffu, sum, o);
    const float inv = 1.0f / sum;
#pragma unroll
    for (int i = 0; i < 32; i++) g_relp[rbase + lane + i * 32] = vals[i] * inv;
}

// ---------------------------------------------------------------------------
// Kernel 1: HMMA bf16-split projection GEMM (emits bf16 hi/lo QKV).
// ---------------------------------------------------------------------------
constexpr int PROJ_SMEM = 4 * 16384;   // 64KB dynamic

__device__ __forceinline__ void load_slab_part(const __nv_bfloat16* __restrict__ src,
                                               int row0, int k0, char* dst, int tid) {
#pragma unroll
    for (int it = 0; it < 4; it++) {
        const int c = tid + it * 256;          // 0..1023 16B-chunks
        const int r = c >> 3;                  // 0..127
        const int e8 = (c & 7) * 8;            // bf16 element offset in row
        const uint4 v = *(const uint4*)(src + (size_t)(row0 + r) * PD + k0 + e8);
        *(uint4*)(dst + SWZ128(r * 128 + e8 * 2)) = v;
    }
}

__global__ __launch_bounds__(256, 2)
void proj_mma_kernel(const float* __restrict__ bq, const float* __restrict__ bk,
                     const float* __restrict__ bv)
{
    extern __shared__ char sm[];
    __shared__ float bias_s[128];

    const int tid  = threadIdx.x;
    const int warp = tid >> 5;
    const int lane = tid & 31;
    const int wm = warp >> 2;
    const int wn = warp & 3;
    const int z  = blockIdx.z;
    const int n0 = blockIdx.x * 128;
    const int m0 = blockIdx.y * 128;

    const __nv_bfloat16* xhi = g_xhi + (size_t)z * XE;
    const __nv_bfloat16* xlo = g_xlo + (size_t)z * XE;
    const __nv_bfloat16* whi = g_whi + (size_t)z * WE;
    const __nv_bfloat16* wlo = g_wlo + (size_t)z * WE;
    const float* bias = (z == 0) ? bq : (z == 1) ? bk : bv;
    __nv_bfloat16* ohi = (z == 0) ? g_qhi : (z == 1) ? g_khi : g_vhi;
    __nv_bfloat16* olo = (z == 0) ? g_qlo : (z == 1) ? g_klo : g_vlo;

    if (tid < 128) bias_s[tid] = bias[n0 + tid];

    char* Ahi_s = sm;
    char* Alo_s = sm + 16384;
    char* Bhi_s = sm + 32768;
    char* Blo_s = sm + 49152;
    const uint32_t uAhi = smem_to_u32(Ahi_s);
    const uint32_t uAlo = smem_to_u32(Alo_s);
    const uint32_t uBhi = smem_to_u32(Bhi_s);
    const uint32_t uBlo = smem_to_u32(Blo_s);

    float acc[4][4][4];
#pragma unroll
    for (int i = 0; i < 4; i++)
#pragma unroll
        for (int j = 0; j < 4; j++)
#pragma unroll
            for (int c = 0; c < 4; c++) acc[i][j][c] = 0.0f;

    const int lrow  = lane & 15;
    const int lcolb = (lane >> 4) * 16;

    for (int s = 0; s < 12; s++) {
        __syncthreads();
        const int k0 = s * 64;
        load_slab_part(xhi, m0, k0, Ahi_s, tid);
        load_slab_part(xlo, m0, k0, Alo_s, tid);
        load_slab_part(whi, n0, k0, Bhi_s, tid);
        load_slab_part(wlo, n0, k0, Blo_s, tid);
        __syncthreads();
#pragma unroll
        for (int ks = 0; ks < 4; ks++) {
            const int kb = ks * 32 + lcolb;
            uint32_t bhi[2][4], blo[2][4];
#pragma unroll
            for (int nt2 = 0; nt2 < 2; nt2++) {
                const int brow = wn * 32 + nt2 * 16 + lrow;
                ldmx4(bhi[nt2], uBhi + SWZ128(brow * 128 + kb));
                ldmx4(blo[nt2], uBlo + SWZ128(brow * 128 + kb));
            }
#pragma unroll
            for (int mt = 0; mt < 4; mt++) {
                const int arow = wm * 64 + mt * 16 + lrow;
                uint32_t a[4];
                ldmx4(a, uAhi + SWZ128(arow * 128 + kb));       // Ahi
#pragma unroll
                for (int nt2 = 0; nt2 < 2; nt2++)
#pragma unroll
                    for (int j = 0; j < 2; j++) {
                        mma16816(acc[mt][nt2 * 2 + j], a, bhi[nt2][j], bhi[nt2][2 + j]);
                        mma16816(acc[mt][nt2 * 2 + j], a, blo[nt2][j], blo[nt2][2 + j]);
                    }
                ldmx4(a, uAlo + SWZ128(arow * 128 + kb));       // Alo
#pragma unroll
                for (int nt2 = 0; nt2 < 2; nt2++)
#pragma unroll
                    for (int j = 0; j < 2; j++)
                        mma16816(acc[mt][nt2 * 2 + j], a, bhi[nt2][j], bhi[nt2][2 + j]);
            }
        }
    }

    // Epilogue: +bias, split to bf16 hi/lo, scatter [b][h][s][hd]
    const int g   = lane >> 2;
    const int tg2 = (lane & 3) * 2;
#pragma unroll
    for (int mt = 0; mt < 4; mt++) {
#pragma unroll
        for (int nt = 0; nt < 4; nt++) {
            const int nc = wn * 32 + nt * 8 + tg2;
            const int n = n0 + nc;
            const int h = n >> 6, hd = n & 63;
            const int m = m0 + wm * 64 + mt * 16 + g;
            const int b = m >> 10, sq = m & 1023;
#pragma unroll
            for (int cc = 0; cc < 2; cc++) {
                const float y0 = acc[mt][nt][cc * 2 + 0] + bias_s[nc];
                const float y1 = acc[mt][nt][cc * 2 + 1] + bias_s[nc + 1];
                const __nv_bfloat16 h0 = __float2bfloat16_rn(y0);
                const __nv_bfloat16 h1 = __float2bfloat16_rn(y1);
                const size_t di = (((size_t)(b * PH + h)) * PS + sq + cc * 8) * PHD + hd;
                *(__nv_bfloat162*)(ohi + di) = __halves2bfloat162(h0, h1);
                *(__nv_bfloat162*)(olo + di) = __floats2bfloat162_rn(
                    y0 - __bfloat162float(h0), y1 - __bfloat162float(h1));
            }
        }
    }
}

// ---------------------------------------------------------------------------
// V transpose: [b][h][s][hd] -> [b][h][hd][s] (hi and lo)
// ---------------------------------------------------------------------------
__global__ void vtrans_kernel() {
    __shared__ __nv_bfloat16 th[64][65], tl[64][65];
    const int tid = threadIdx.x;
    const int bh = blockIdx.y;
    const int st = blockIdx.x * 64;
    const size_t src0 = ((size_t)bh * PS + st) * PHD;
#pragma unroll
    for (int it = 0; it < 16; it++) {
        const int i = tid + it * 256;
        const int s = i >> 6, hd = i & 63;
        th[hd][s] = g_vhi[src0 + (size_t)s * PHD + hd];
        tl[hd][s] = g_vlo[src0 + (size_t)s * PHD + hd];
    }
    __syncthreads();
    const size_t dst0 = (size_t)bh * PHD * PS + st;
#pragma unroll
    for (int it = 0; it < 16; it++) {
        const int i = tid + it * 256;
        const int hd = i >> 6, s = i & 63;
        g_vthi[dst0 + (size_t)hd * PS + s] = th[hd][s];
        g_vtlo[dst0 + (size_t)hd * PS + s] = tl[hd][s];
    }
}

// ---------------------------------------------------------------------------
// Kernel 2: HMMA scores, 16 q-rows per CTA, occ-2.
// All 8 warps share the 16 A-rows; warp w owns k-cols [w*16, w*16+16) of each
// 128-key slab. Mask applied inline from gmem (L2-hot: 12 heads reuse a row).
// smem: sbuf f32[16][1028] @0 (65792), qhi@65792(2048), qlo@67840(2048),
//       khi@69888(16384), klo@86272(16384) = 102656  -> 2 CTAs/SM
// ---------------------------------------------------------------------------
constexpr int SC_SMEM = 102656;
constexpr int SC_QHI = 65792, SC_QLO = 67840, SC_KHI = 69888, SC_KLO = 86272;

__global__ __launch_bounds__(256, 2)
void scores_mma_kernel(const void* __restrict__ mask, const float* __restrict__ l1p,
                       float* __restrict__ prob)
{
    extern __shared__ char sm2[];
    float* sbuf = (float*)sm2;
    char* qhi_s = sm2 + SC_QHI;
    char* qlo_s = sm2 + SC_QLO;
    char* khi_s = sm2 + SC_KHI;
    char* klo_s = sm2 + SC_KLO;
    const uint32_t uQhi = smem_to_u32(qhi_s);
    const uint32_t uQlo = smem_to_u32(qlo_s);
    const uint32_t uKhi = smem_to_u32(khi_s);
    const uint32_t uKlo = smem_to_u32(klo_s);

    const int tid  = threadIdx.x;
    const int warp = tid >> 5;
    const int lane = tid & 31;
    const int bh = blockIdx.y;
    const int b = bh / PH, h = bh % PH;
    const int q0 = blockIdx.x * 16;
    const int mmode = g_mask_mode;
    const float l1 = *l1p;
    const float w0 = 1.0f - l1;

    // Q tile (16 x 64) hi+lo: 128 16B-chunks each
    {
        const size_t qoff = ((size_t)bh * PS + q0) * PHD;
        if (tid < 128) {
            const int r = tid >> 3, e8 = (tid & 7) * 8;
            *(uint4*)(qhi_s + SWZ128(r * 128 + e8 * 2)) =
                *(const uint4*)(g_qhi + qoff + (size_t)r * PHD + e8);
        } else {
            const int t = tid - 128;
            const int r = t >> 3, e8 = (t & 7) * 8;
            *(uint4*)(qlo_s + SWZ128(r * 128 + e8 * 2)) =
                *(const uint4*)(g_qlo + qoff + (size_t)r * PHD + e8);
        }
    }

    const int lrow  = lane & 15;
    const int lcolb = (lane >> 4) * 16;
    const int g   = lane >> 2;
    const int tg2 = (lane & 3) * 2;
    const size_t kbh  = (size_t)bh * PS * PHD;
    const size_t mrow = ((size_t)b * PS + q0) * PS;

    for (int kc0 = 0; kc0 < PS; kc0 += 128) {
        __syncthreads();
        // K slab 128 x 64, hi+lo
#pragma unroll
        for (int it = 0; it < 4; it++) {
            const int c = tid + it * 256;
            const int r = c >> 3, e8 = (c & 7) * 8;
            *(uint4*)(khi_s + SWZ128(r * 128 + e8 * 2)) =
                *(const uint4*)(g_khi + kbh + (size_t)(kc0 + r) * PHD + e8);
            *(uint4*)(klo_s + SWZ128(r * 128 + e8 * 2)) =
                *(const uint4*)(g_klo + kbh + (size_t)(kc0 + r) * PHD + e8);
        }
        __syncthreads();

        float acc[2][4];
#pragma unroll
        for (int j = 0; j < 2; j++)
#pragma unroll
            for (int c = 0; c < 4; c++) acc[j][c] = 0.0f;
#pragma unroll
        for (int ks = 0; ks < 4; ks++) {
            const int kb = ks * 32 + lcolb;
            uint32_t bhf[4], blf[4], ahf[4], alf[4];
            const int brow = warp * 16 + lrow;
            ldmx4(bhf, uKhi + SWZ128(brow * 128 + kb));
            ldmx4(blf, uKlo + SWZ128(brow * 128 + kb));
            ldmx4(ahf, uQhi + SWZ128(lrow * 128 + kb));
            ldmx4(alf, uQlo + SWZ128(lrow * 128 + kb));
#pragma unroll
            for (int j = 0; j < 2; j++) {
                mma16816(acc[j], ahf, bhf[j], bhf[2 + j]);
                mma16816(acc[j], ahf, blf[j], blf[2 + j]);
                mma16816(acc[j], alf, bhf[j], bhf[2 + j]);
            }
        }
        // epilogue: inline mask + scale -> sbuf
        const int r0 = g, r1 = g + 8;
#pragma unroll
        for (int j = 0; j < 2; j++) {
            const int kcol = kc0 + warp * 16 + j * 8 + tg2;
            const size_t mi0 = mrow + (size_t)r0 * PS + kcol;
            const size_t mi1 = mrow + (size_t)r1 * PS + kcol;
            sbuf[r0 * 1028 + kcol]     = read_mask(mask, mi0,     mmode) ? -1.0e9f : acc[j][0] * 0.125f;
            sbuf[r0 * 1028 + kcol + 1] = read_mask(mask, mi0 + 1, mmode) ? -1.0e9f : acc[j][1] * 0.125f;
            sbuf[r1 * 1028 + kcol]     = read_mask(mask, mi1,     mmode) ? -1.0e9f : acc[j][2] * 0.125f;
            sbuf[r1 * 1028 + kcol + 1] = read_mask(mask, mi1 + 1, mmode) ? -1.0e9f : acc[j][3] * 0.125f;
        }
    }
    __syncthreads();

    // softmax + combine + write prob. Each warp: rows 2*warp, 2*warp+1.
#pragma unroll
    for (int rr = 0; rr < 2; rr++) {
        const int r = warp * 2 + rr;
        float vals[32];
        float mx = -3.0e38f;
#pragma unroll
        for (int i = 0; i < 32; i++) {
            vals[i] = sbuf[r * 1028 + lane + i * 32];
            mx = fmaxf(mx, vals[i]);
        }
#pragma unroll
        for (int o = 16; o; o >>= 1) mx = fmaxf(mx, __shfl_xor_sync(0xffffffffu, mx, o));
        float sum = 0.0f;
#pragma unroll
        for (int i = 0; i < 32; i++) { vals[i] = __expf(vals[i] - mx); sum += vals[i]; }
#pragma unroll
        for (int o = 16; o; o >>= 1) sum += __shfl_xor_sync(0xffffffffu, sum, o);
        const float inv = 1.0f / sum;
        const size_t pb = (((size_t)(b * PH + h)) * PS + q0 + r) * PS;
        const float* rp = g_relp + ((size_t)b * PS + q0 + r) * PS;
#pragma unroll
        for (int i = 0; i < 32; i++) {
            const int c = lane + i * 32;
            prob[pb + c] = w0 * vals[i] * inv + l1 * rp[c];
        }
    }
}

// ---------------------------------------------------------------------------
// Kernel 3: HMMA pv. out = prob @ V per (b,h). CTA 128q x 64hd, K-slab 64.
// (unchanged from R8 best)
// ---------------------------------------------------------------------------
constexpr int PV_SMEM = 49152;

__global__ __launch_bounds__(256, 2)
void pv_mma_kernel(const float* __restrict__ prob, float* __restrict__ outp)
{
    extern __shared__ char sm3[];
    char* phi_s = sm3;
    char* plo_s = sm3 + 16384;
    char* vhi_s = sm3 + 32768;
    char* vlo_s = sm3 + 40960;
    const uint32_t uPhi = smem_to_u32(phi_s);
    const uint32_t uPlo = smem_to_u32(plo_s);
    const uint32_t uVhi = smem_to_u32(vhi_s);
    const uint32_t uVlo = smem_to_u32(vlo_s);

    const int tid  = threadIdx.x;
    const int warp = tid >> 5;
    const int lane = tid & 31;
    const int wm = warp >> 1;          // 0..3 (32 q rows)
    const int wn = warp & 1;           // 0..1 (32 hd cols)
    const int bh = blockIdx.y;
    const int b = bh / PH, h = bh % PH;
    const int q0 = blockIdx.x * 128;

    const size_t pbase = ((size_t)bh * PS + q0) * PS;
    const size_t vtb = (size_t)bh * PHD * PS;

    float acc[2][4][4];
#pragma unroll
    for (int i = 0; i < 2; i++)
#pragma unroll
        for (int j = 0; j < 4; j++)
#pragma unroll
            for (int c = 0; c < 4; c++) acc[i][j][c] = 0.0f;

    const int lrow  = lane & 15;
    const int lcolb = (lane >> 4) * 16;

    for (int kc0 = 0; kc0 < PS; kc0 += 64) {
        __syncthreads();
        // prob tile [128 q][64 k] fp32 -> bf16 hi/lo swizzled
#pragma unroll
        for (int it = 0; it < 8; it++) {
            const int c = tid + it * 256;          // 0..2047 float4 chunks
            const int q = c >> 4, k4 = (c & 15) * 4;
            const float4 v = *(const float4*)(prob + pbase + (size_t)q * PS + kc0 + k4);
            const __nv_bfloat16 h0 = __float2bfloat16_rn(v.x);
            const __nv_bfloat16 h1 = __float2bfloat16_rn(v.y);
            const __nv_bfloat16 h2 = __float2bfloat16_rn(v.z);
            const __nv_bfloat16 h3 = __float2bfloat16_rn(v.w);
            __nv_bfloat162 hp01 = __halves2bfloat162(h0, h1);
            __nv_bfloat162 hp23 = __halves2bfloat162(h2, h3);
            __nv_bfloat162 lp01 = __floats2bfloat162_rn(v.x - __bfloat162float(h0),
                                                        v.y - __bfloat162float(h1));
            __nv_bfloat162 lp23 = __floats2bfloat162_rn(v.z - __bfloat162float(h2),
                                                        v.w - __bfloat162float(h3));
            uint2 hv, lv;
            hv.x = *reinterpret_cast<uint32_t*>(&hp01);
            hv.y = *reinterpret_cast<uint32_t*>(&hp23);
            lv.x = *reinterpret_cast<uint32_t*>(&lp01);
            lv.y = *reinterpret_cast<uint32_t*>(&lp23);
            *(uint2*)(phi_s + SWZ128(q * 128 + k4 * 2)) = hv;
            *(uint2*)(plo_s + SWZ128(q * 128 + k4 * 2)) = lv;
        }
        // vT slab [64 hd][64 k]
#pragma unroll
        for (int it = 0; it < 2; it++) {
            const int c = tid + it * 256;          // 0..511 16B chunks
            const int r = c >> 3, e8 = (c & 7) * 8;
            *(uint4*)(vhi_s + SWZ128(r * 128 + e8 * 2)) =
                *(const uint4*)(g_vthi + vtb + (size_t)r * PS + kc0 + e8);
            *(uint4*)(vlo_s + SWZ128(r * 128 + e8 * 2)) =
                *(const uint4*)(g_vtlo + vtb + (size_t)r * PS + kc0 + e8);
        }
        __syncthreads();
#pragma unroll
        for (int ks = 0; ks < 4; ks++) {
            const int kb = ks * 32 + lcolb;
            uint32_t bhi[2][4], blo[2][4];
#pragma unroll
            for (int nt2 = 0; nt2 < 2; nt2++) {
                const int brow = wn * 32 + nt2 * 16 + lrow;
                ldmx4(bhi[nt2], uVhi + SWZ128(brow * 128 + kb));
                ldmx4(blo[nt2], uVlo + SWZ128(brow * 128 + kb));
            }
#pragma unroll
            for (int mt = 0; mt < 2; mt++) {
                const int arow = wm * 32 + mt * 16 + lrow;
                uint32_t a[4];
                ldmx4(a, uPhi + SWZ128(arow * 128 + kb));
#pragma unroll
                for (int nt2 = 0; nt2 < 2; nt2++)
#pragma unroll
                    for (int j = 0; j < 2; j++) {
                        mma16816(acc[mt][nt2 * 2 + j], a, bhi[nt2][j], bhi[nt2][2 + j]);
                        mma16816(acc[mt][nt2 * 2 + j], a, blo[nt2][j], blo[nt2][2 + j]);
                    }
                ldmx4(a, uPlo + SWZ128(arow * 128 + kb));
#pragma unroll
                for (int nt2 = 0; nt2 < 2; nt2++)
#pragma unroll
                    for (int j = 0; j < 2; j++)
                        mma16816(acc[mt][nt2 * 2 + j], a, bhi[nt2][j], bhi[nt2][2 + j]);
            }
        }
    }
    // epilogue
    const int g   = lane >> 2;
    const int tg2 = (lane & 3) * 2;
#pragma unroll
    for (int mt = 0; mt < 2; mt++) {
#pragma unroll
        for (int nt = 0; nt < 4; nt++) {
            const int nc = wn * 32 + nt * 8 + tg2;
            const int m = q0 + wm * 32 + mt * 16 + g;
            float2 v0, v1;
            v0.x = acc[mt][nt][0]; v0.y = acc[mt][nt][1];
            v1.x = acc[mt][nt][2]; v1.y = acc[mt][nt][3];
            *(float2*)(outp + ((size_t)b * PS + m) * PD + h * PHD + nc)     = v0;
            *(float2*)(outp + ((size_t)b * PS + m + 8) * PD + h * PHD + nc) = v1;
        }
    }
}

// ---------------------------------------------------------------------------
extern "C" void kernel_launch(void* const* d_in, const int* in_sizes, int n_in,
                              void* d_out, int out_size) {
    const float* query = (const float*)d_in[0];
    const float* key   = (const float*)d_in[1];
    const float* value = (const float*)d_in[2];
    const float* rel   = (const float*)d_in[3];
    const void*  mask  = d_in[4];
    const float* l1    = (const float*)d_in[5];
    const float* Wq    = (const float*)d_in[6];
    const float* bq    = (const float*)d_in[7];
    const float* Wk    = (const float*)d_in[8];
    const float* bk    = (const float*)d_in[9];
    const float* Wv    = (const float*)d_in[10];
    const float* bv    = (const float*)d_in[11];

    float* outp = (float*)d_out;
    float* prob = outp + OUT_ELEMS;

    detect_mask_kernel<<<1, 256>>>(mask);

    conv_x_kernel<<<dim3((unsigned)(XE / 512), 3), 256>>>(query, key, value);
    conv_w_kernel<<<dim3((unsigned)(WE / 512), 3), 256>>>(Wq, Wk, Wv);
    relp_kernel<<<1024, 256>>>(rel, mask);

    cudaFuncSetAttribute(proj_mma_kernel,
                         cudaFuncAttributeMaxDynamicSharedMemorySize, PROJ_SMEM);
    dim3 g1(PD / 128, (PB * PS) / 128, 3);     // (6, 64, 3)
    proj_mma_kernel<<<g1, 256, PROJ_SMEM>>>(bq, bk, bv);

    vtrans_kernel<<<dim3(16, PB * PH), 256>>>();

    cudaFuncSetAttribute(scores_mma_kernel,
                         cudaFuncAttributeMaxDynamicSharedMemorySize, SC_SMEM);
    dim3 g2(PS / 16, PB * PH);                 // (64, 96)
    scores_mma_kernel<<<g2, 256, SC_SMEM>>>(mask, l1, prob);

    cudaFuncSetAttribute(pv_mma_kernel,
                         cudaFuncAttributeMaxDynamicSharedMemorySize, PV_SMEM);
    dim3 g3(PS / 128, PB * PH);                // (8, 96)
    pv_mma_kernel<<<g3, 256, PV_SMEM>>>(prob, outp);
}

// round 11
// speedup vs baseline: 2.0134x; 1.7535x over previous
#include <cuda_runtime.h>
#include <cuda_bf16.h>
#include <cstdint>
#include <cstddef>

// Problem constants
constexpr int PB = 8, PS = 1024, PD = 768, PH = 12, PHD = 64;
constexpr size_t QKV_ELEMS = (size_t)PB * PH * PS * PHD;        // 6,291,456
constexpr size_t OUT_ELEMS = (size_t)PB * PS * PD;              // 6,291,456
constexpr size_t XE = (size_t)PB * PS * PD;                     // per matrix
constexpr size_t WE = (size_t)PD * PD;                          // per matrix
constexpr size_t RELP_ELEMS = (size_t)PB * PS * PS;             // 8,388,608

// Scratch (no allocations allowed -> __device__ globals)
__device__ __nv_bfloat16 g_xhi[3 * XE];
__device__ __nv_bfloat16 g_xlo[3 * XE];
__device__ __nv_bfloat16 g_whi[3 * WE];
__device__ __nv_bfloat16 g_wlo[3 * WE];
__device__ __nv_bfloat16 g_qhi[QKV_ELEMS], g_qlo[QKV_ELEMS];
__device__ __nv_bfloat16 g_khi[QKV_ELEMS], g_klo[QKV_ELEMS];
__device__ __nv_bfloat16 g_vhi[QKV_ELEMS], g_vlo[QKV_ELEMS];
__device__ __nv_bfloat16 g_vthi[QKV_ELEMS], g_vtlo[QKV_ELEMS];   // [b][h][hd][s]
__device__ float g_relp[RELP_ELEMS];
__device__ int   g_mask_mode;   // 0 = uint8/bool, 1 = int32, 2 = float32

// ---------------------------------------------------------------------------
// Tensor-core helpers (portable sm_80+ path: ldmatrix + mma.sync bf16)
// ---------------------------------------------------------------------------
__device__ __forceinline__ uint32_t smem_to_u32(const void* p) {
    uint32_t a;
    asm("{ .reg .u64 t; cvta.to.shared.u64 t, %1; cvt.u32.u64 %0, t; }" : "=r"(a) : "l"(p));
    return a;
}
__device__ __forceinline__ void ldmx4(uint32_t* r, uint32_t addr) {
    asm volatile("ldmatrix.sync.aligned.m8n8.x4.shared.b16 {%0,%1,%2,%3}, [%4];"
        : "=r"(r[0]), "=r"(r[1]), "=r"(r[2]), "=r"(r[3]) : "r"(addr));
}
__device__ __forceinline__ void mma16816(float* c, const uint32_t* a, uint32_t b0, uint32_t b1) {
    asm volatile("mma.sync.aligned.m16n8k16.row.col.f32.bf16.bf16.f32 "
        "{%0,%1,%2,%3}, {%4,%5,%6,%7}, {%8,%9}, {%0,%1,%2,%3};"
        : "+f"(c[0]), "+f"(c[1]), "+f"(c[2]), "+f"(c[3])
        : "r"(a[0]), "r"(a[1]), "r"(a[2]), "r"(a[3]), "r"(b0), "r"(b1));
}
#define SWZ128(off) ((off) ^ (((off) >> 3) & 0x70))

// ---------------------------------------------------------------------------
// Mask dtype probe (deterministic)
// ---------------------------------------------------------------------------
__global__ void detect_mask_kernel(const void* __restrict__ mask) {
    __shared__ int sawFloat, sawOther;
    if (threadIdx.x == 0) { sawFloat = 0; sawOther = 0; }
    __syncthreads();
    const unsigned int* w = (const unsigned int*)mask;
    int lf = 0, lo = 0;
    for (int i = threadIdx.x; i < 2048; i += blockDim.x) {
        unsigned int x = w[i];
        if (x == 0x3F800000u) lf = 1;
        else if (x > 1u) lo = 1;
    }
    if (lf) atomicOr(&sawFloat, 1);
    if (lo) atomicOr(&sawOther, 1);
    __syncthreads();
    if (threadIdx.x == 0) g_mask_mode = sawFloat ? 2 : (sawOther ? 0 : 1);
}

__device__ __forceinline__ bool read_mask(const void* m, size_t idx, int mode) {
    if (mode == 0) return ((const unsigned char*)m)[idx] != 0;
    if (mode == 1) return ((const int*)m)[idx] != 0;
    return ((const float*)m)[idx] != 0.0f;
}

// ---------------------------------------------------------------------------
// Conversion kernels: fp32 -> (bf16 hi, bf16 lo) split
// ---------------------------------------------------------------------------
__global__ void conv_x_kernel(const float* __restrict__ q, const float* __restrict__ k,
                              const float* __restrict__ v) {
    const int z = blockIdx.y;
    const float* src = (z == 0) ? q : (z == 1) ? k : v;
    __nv_bfloat16* hi = g_xhi + (size_t)z * XE;
    __nv_bfloat16* lo = g_xlo + (size_t)z * XE;
    const size_t i2 = ((size_t)blockIdx.x * blockDim.x + threadIdx.x) * 2;
    if (i2 + 1 >= XE) return;
    const float2 s = *(const float2*)(src + i2);
    const __nv_bfloat16 h0 = __float2bfloat16_rn(s.x);
    const __nv_bfloat16 h1 = __float2bfloat16_rn(s.y);
    *(__nv_bfloat162*)(hi + i2) = __halves2bfloat162(h0, h1);
    *(__nv_bfloat162*)(lo + i2) = __floats2bfloat162_rn(
        s.x - __bfloat162float(h0), s.y - __bfloat162float(h1));
}

__global__ void conv_w_kernel(const float* __restrict__ wq, const float* __restrict__ wk,
                              const float* __restrict__ wv) {
    const int z = blockIdx.y;
    const float* src = (z == 0) ? wq : (z == 1) ? wk : wv;
    __nv_bfloat16* hi = g_whi + (size_t)z * WE;
    __nv_bfloat16* lo = g_wlo + (size_t)z * WE;
    const size_t i2 = ((size_t)blockIdx.x * blockDim.x + threadIdx.x) * 2;
    if (i2 + 1 >= WE) return;
    const float2 s = *(const float2*)(src + i2);
    const __nv_bfloat16 h0 = __float2bfloat16_rn(s.x);
    const __nv_bfloat16 h1 = __float2bfloat16_rn(s.y);
    *(__nv_bfloat162*)(hi + i2) = __halves2bfloat162(h0, h1);
    *(__nv_bfloat162*)(lo + i2) = __floats2bfloat162_rn(
        s.x - __bfloat162float(h0), s.y - __bfloat162float(h1));
}

// ---------------------------------------------------------------------------
// relp kernel: rel_attn = softmax(where(rel*mask==0, -1e4, rel*mask)) per row.
// ---------------------------------------------------------------------------
__global__ void relp_kernel(const float* __restrict__ rel, const void* __restrict__ mask) {
    const int lane = threadIdx.x & 31;
    const int warp = threadIdx.x >> 5;
    const int row = blockIdx.x * 8 + warp;          // 0..8191 = b*1024+s
    const size_t rbase = (size_t)row * PS;
    const int mmode = g_mask_mode;
    float vals[32];
    float mx = -3.0e38f;
#pragma unroll
    for (int i = 0; i < 32; i++) {
        const int c = lane + i * 32;
        const bool m = read_mask(mask, rbase + c, mmode);
        const float v = rel[rbase + c];
        const float relm = m ? v : 0.0f;
        const float logit = (relm == 0.0f) ? -10000.0f : relm;
        vals[i] = logit;
        mx = fmaxf(mx, logit);
    }
#pragma unroll
    for (int o = 16; o; o >>= 1) mx = fmaxf(mx, __shfl_xor_sync(0xffffffffu, mx, o));
    float sum = 0.0f;
#pragma unroll
    for (int i = 0; i < 32; i++) { vals[i] = __expf(vals[i] - mx); sum += vals[i]; }
#pragma unroll
    for (int o = 16; o; o >>= 1) sum += __shfl_xor_sync(0xffffffffu, sum, o);
    const float inv = 1.0f / sum;
#pragma unroll
    for (int i = 0; i < 32; i++) g_relp[rbase + lane + i * 32] = vals[i] * inv;
}

// ---------------------------------------------------------------------------
// Kernel 1: HMMA bf16-split projection GEMM (emits bf16 hi/lo QKV).
// ---------------------------------------------------------------------------
constexpr int PROJ_SMEM = 4 * 16384;   // 64KB dynamic

__device__ __forceinline__ void load_slab_part(const __nv_bfloat16* __restrict__ src,
                                               int row0, int k0, char* dst, int tid) {
#pragma unroll
    for (int it = 0; it < 4; it++) {
        const int c = tid + it * 256;          // 0..1023 16B-chunks
        const int r = c >> 3;                  // 0..127
        const int e8 = (c & 7) * 8;            // bf16 element offset in row
        const uint4 v = *(const uint4*)(src + (size_t)(row0 + r) * PD + k0 + e8);
        *(uint4*)(dst + SWZ128(r * 128 + e8 * 2)) = v;
    }
}

// Load a [128 x 64] bf16 tile whose rows are contiguous 64-element (128B) rows.
__device__ __forceinline__ void load_tile64(const __nv_bfloat16* __restrict__ src,
                                            size_t base, char* dst, int tid) {
#pragma unroll
    for (int it = 0; it < 4; it++) {
        const int c = tid + it * 256;          // 0..1023 16B-chunks
        const int r = c >> 3;                  // 0..127
        const int e8 = (c & 7) * 8;
        const uint4 v = *(const uint4*)(src + base + (size_t)r * 64 + e8);
        *(uint4*)(dst + SWZ128(r * 128 + e8 * 2)) = v;
    }
}

__global__ __launch_bounds__(256, 2)
void proj_mma_kernel(const float* __restrict__ bq, const float* __restrict__ bk,
                     const float* __restrict__ bv)
{
    extern __shared__ char sm[];
    __shared__ float bias_s[128];

    const int tid  = threadIdx.x;
    const int warp = tid >> 5;
    const int lane = tid & 31;
    const int wm = warp >> 2;
    const int wn = warp & 3;
    const int z  = blockIdx.z;
    const int n0 = blockIdx.x * 128;
    const int m0 = blockIdx.y * 128;

    const __nv_bfloat16* xhi = g_xhi + (size_t)z * XE;
    const __nv_bfloat16* xlo = g_xlo + (size_t)z * XE;
    const __nv_bfloat16* whi = g_whi + (size_t)z * WE;
    const __nv_bfloat16* wlo = g_wlo + (size_t)z * WE;
    const float* bias = (z == 0) ? bq : (z == 1) ? bk : bv;
    __nv_bfloat16* ohi = (z == 0) ? g_qhi : (z == 1) ? g_khi : g_vhi;
    __nv_bfloat16* olo = (z == 0) ? g_qlo : (z == 1) ? g_klo : g_vlo;

    if (tid < 128) bias_s[tid] = bias[n0 + tid];

    char* Ahi_s = sm;
    char* Alo_s = sm + 16384;
    char* Bhi_s = sm + 32768;
    char* Blo_s = sm + 49152;
    const uint32_t uAhi = smem_to_u32(Ahi_s);
    const uint32_t uAlo = smem_to_u32(Alo_s);
    const uint32_t uBhi = smem_to_u32(Bhi_s);
    const uint32_t uBlo = smem_to_u32(Blo_s);

    float acc[4][4][4];
#pragma unroll
    for (int i = 0; i < 4; i++)
#pragma unroll
        for (int j = 0; j < 4; j++)
#pragma unroll
            for (int c = 0; c < 4; c++) acc[i][j][c] = 0.0f;

    const int lrow  = lane & 15;
    const int lcolb = (lane >> 4) * 16;

    for (int s = 0; s < 12; s++) {
        __syncthreads();
        const int k0 = s * 64;
        load_slab_part(xhi, m0, k0, Ahi_s, tid);
        load_slab_part(xlo, m0, k0, Alo_s, tid);
        load_slab_part(whi, n0, k0, Bhi_s, tid);
        load_slab_part(wlo, n0, k0, Blo_s, tid);
        __syncthreads();
#pragma unroll
        for (int ks = 0; ks < 4; ks++) {
            const int kb = ks * 32 + lcolb;
            uint32_t bhi[2][4], blo[2][4];
#pragma unroll
            for (int nt2 = 0; nt2 < 2; nt2++) {
                const int brow = wn * 32 + nt2 * 16 + lrow;
                ldmx4(bhi[nt2], uBhi + SWZ128(brow * 128 + kb));
                ldmx4(blo[nt2], uBlo + SWZ128(brow * 128 + kb));
            }
#pragma unroll
            for (int mt = 0; mt < 4; mt++) {
                const int arow = wm * 64 + mt * 16 + lrow;
                uint32_t a[4];
                ldmx4(a, uAhi + SWZ128(arow * 128 + kb));       // Ahi
#pragma unroll
                for (int nt2 = 0; nt2 < 2; nt2++)
#pragma unroll
                    for (int j = 0; j < 2; j++) {
                        mma16816(acc[mt][nt2 * 2 + j], a, bhi[nt2][j], bhi[nt2][2 + j]);
                        mma16816(acc[mt][nt2 * 2 + j], a, blo[nt2][j], blo[nt2][2 + j]);
                    }
                ldmx4(a, uAlo + SWZ128(arow * 128 + kb));       // Alo
#pragma unroll
                for (int nt2 = 0; nt2 < 2; nt2++)
#pragma unroll
                    for (int j = 0; j < 2; j++)
                        mma16816(acc[mt][nt2 * 2 + j], a, bhi[nt2][j], bhi[nt2][2 + j]);
            }
        }
    }

    // Epilogue: +bias, split to bf16 hi/lo, scatter [b][h][s][hd]
    const int g   = lane >> 2;
    const int tg2 = (lane & 3) * 2;
#pragma unroll
    for (int mt = 0; mt < 4; mt++) {
#pragma unroll
        for (int nt = 0; nt < 4; nt++) {
            const int nc = wn * 32 + nt * 8 + tg2;
            const int n = n0 + nc;
            const int h = n >> 6, hd = n & 63;
            const int m = m0 + wm * 64 + mt * 16 + g;
            const int b = m >> 10, sq = m & 1023;
#pragma unroll
            for (int cc = 0; cc < 2; cc++) {
                const float y0 = acc[mt][nt][cc * 2 + 0] + bias_s[nc];
                const float y1 = acc[mt][nt][cc * 2 + 1] + bias_s[nc + 1];
                const __nv_bfloat16 h0 = __float2bfloat16_rn(y0);
                const __nv_bfloat16 h1 = __float2bfloat16_rn(y1);
                const size_t di = (((size_t)(b * PH + h)) * PS + sq + cc * 8) * PHD + hd;
                *(__nv_bfloat162*)(ohi + di) = __halves2bfloat162(h0, h1);
                *(__nv_bfloat162*)(olo + di) = __floats2bfloat162_rn(
                    y0 - __bfloat162float(h0), y1 - __bfloat162float(h1));
            }
        }
    }
}

// ---------------------------------------------------------------------------
// V transpose: [b][h][s][hd] -> [b][h][hd][s] (hi and lo)
// ---------------------------------------------------------------------------
__global__ void vtrans_kernel() {
    __shared__ __nv_bfloat16 th[64][65], tl[64][65];
    const int tid = threadIdx.x;
    const int bh = blockIdx.y;
    const int st = blockIdx.x * 64;
    const size_t src0 = ((size_t)bh * PS + st) * PHD;
#pragma unroll
    for (int it = 0; it < 16; it++) {
        const int i = tid + it * 256;
        const int s = i >> 6, hd = i & 63;
        th[hd][s] = g_vhi[src0 + (size_t)s * PHD + hd];
        tl[hd][s] = g_vlo[src0 + (size_t)s * PHD + hd];
    }
    __syncthreads();
    const size_t dst0 = (size_t)bh * PHD * PS + st;
#pragma unroll
    for (int it = 0; it < 16; it++) {
        const int i = tid + it * 256;
        const int hd = i >> 6, s = i & 63;
        g_vthi[dst0 + (size_t)hd * PS + s] = th[hd][s];
        g_vtlo[dst0 + (size_t)hd * PS + s] = tl[hd][s];
    }
}

// ---------------------------------------------------------------------------
// Kernel 2a: scores GEMM. Per CTA: 128 q x 128 k for one (b,h). Contraction
// dim = 64 (single slab). Writes RAW scores/8 (no mask) to prob.
// smem: Qhi/Qlo/Khi/Klo each [128 x 64] bf16 = 16KB -> 64KB, occ 2.
// ---------------------------------------------------------------------------
constexpr int SG_SMEM = 4 * 16384;

__global__ __launch_bounds__(256, 2)
void scores_gemm_kernel(float* __restrict__ prob)
{
    extern __shared__ char sm4[];
    char* Qhi_s = sm4;
    char* Qlo_s = sm4 + 16384;
    char* Khi_s = sm4 + 32768;
    char* Klo_s = sm4 + 49152;
    const uint32_t uQhi = smem_to_u32(Qhi_s);
    const uint32_t uQlo = smem_to_u32(Qlo_s);
    const uint32_t uKhi = smem_to_u32(Khi_s);
    const uint32_t uKlo = smem_to_u32(Klo_s);

    const int tid  = threadIdx.x;
    const int warp = tid >> 5;
    const int lane = tid & 31;
    const int wm = warp >> 2;      // 0..1 -> 64 q-rows
    const int wn = warp & 3;       // 0..3 -> 32 k-cols
    const int bh = blockIdx.z;
    const int q0 = blockIdx.y * 128;
    const int k0 = blockIdx.x * 128;

    const size_t qb = ((size_t)bh * PS + q0) * PHD;
    const size_t kb0 = ((size_t)bh * PS + k0) * PHD;

    load_tile64(g_qhi, qb, Qhi_s, tid);
    load_tile64(g_qlo, qb, Qlo_s, tid);
    load_tile64(g_khi, kb0, Khi_s, tid);
    load_tile64(g_klo, kb0, Klo_s, tid);
    __syncthreads();

    float acc[4][4][4];
#pragma unroll
    for (int i = 0; i < 4; i++)
#pragma unroll
        for (int j = 0; j < 4; j++)
#pragma unroll
            for (int c = 0; c < 4; c++) acc[i][j][c] = 0.0f;

    const int lrow  = lane & 15;
    const int lcolb = (lane >> 4) * 16;

#pragma unroll
    for (int ks = 0; ks < 4; ks++) {
        const int kb = ks * 32 + lcolb;
        uint32_t bhi[2][4], blo[2][4];
#pragma unroll
        for (int nt2 = 0; nt2 < 2; nt2++) {
            const int brow = wn * 32 + nt2 * 16 + lrow;
            ldmx4(bhi[nt2], uKhi + SWZ128(brow * 128 + kb));
            ldmx4(blo[nt2], uKlo + SWZ128(brow * 128 + kb));
        }
#pragma unroll
        for (int mt = 0; mt < 4; mt++) {
            const int arow = wm * 64 + mt * 16 + lrow;
            uint32_t a[4];
            ldmx4(a, uQhi + SWZ128(arow * 128 + kb));       // Qhi
#pragma unroll
            for (int nt2 = 0; nt2 < 2; nt2++)
#pragma unroll
                for (int j = 0; j < 2; j++) {
                    mma16816(acc[mt][nt2 * 2 + j], a, bhi[nt2][j], bhi[nt2][2 + j]);
                    mma16816(acc[mt][nt2 * 2 + j], a, blo[nt2][j], blo[nt2][2 + j]);
                }
            ldmx4(a, uQlo + SWZ128(arow * 128 + kb));       // Qlo
#pragma unroll
            for (int nt2 = 0; nt2 < 2; nt2++)
#pragma unroll
                for (int j = 0; j < 2; j++)
                    mma16816(acc[mt][nt2 * 2 + j], a, bhi[nt2][j], bhi[nt2][2 + j]);
        }
    }

    // Epilogue: scale by 1/8, write to prob[(bh*PS+q)*PS + k]
    const int g   = lane >> 2;
    const int tg2 = (lane & 3) * 2;
    const size_t pb = (size_t)bh * PS * PS;
#pragma unroll
    for (int mt = 0; mt < 4; mt++) {
#pragma unroll
        for (int nt = 0; nt < 4; nt++) {
            const int kcol = k0 + wn * 32 + nt * 8 + tg2;
            const int qr = q0 + wm * 64 + mt * 16 + g;
            float2 v0, v1;
            v0.x = acc[mt][nt][0] * 0.125f; v0.y = acc[mt][nt][1] * 0.125f;
            v1.x = acc[mt][nt][2] * 0.125f; v1.y = acc[mt][nt][3] * 0.125f;
            *(float2*)(prob + pb + (size_t)qr * PS + kcol)       = v0;
            *(float2*)(prob + pb + (size_t)(qr + 8) * PS + kcol) = v1;
        }
    }
}

// ---------------------------------------------------------------------------
// Kernel 2b: softmax + combine, one warp per (b,h,row), register-resident.
// Reads raw scores from prob, applies mask -> softmax -> blend with relp,
// writes final prob in place.
// ---------------------------------------------------------------------------
__global__ void softmax_combine_kernel(const void* __restrict__ mask,
                                       const float* __restrict__ l1p,
                                       float* __restrict__ prob)
{
    const int lane = threadIdx.x & 31;
    const int warp = threadIdx.x >> 5;
    const int gid = blockIdx.x * 8 + warp;          // 0..98303 = bh*1024 + r
    const int bh = gid >> 10, r = gid & 1023;
    const int b = bh / PH;
    const size_t pb = (size_t)gid * PS;
    const size_t mrow = ((size_t)b * PS + r) * PS;  // index into mask AND relp
    const int mmode = g_mask_mode;
    const float l1 = *l1p;
    const float w0 = 1.0f - l1;

    float vals[32];
    float mx = -3.0e38f;
#pragma unroll
    for (int i = 0; i < 32; i++) {
        const int c = lane + i * 32;
        const float s = prob[pb + c];
        vals[i] = read_mask(mask, mrow + c, mmode) ? -1.0e9f : s;
        mx = fmaxf(mx, vals[i]);
    }
#pragma unroll
    for (int o = 16; o; o >>= 1) mx = fmaxf(mx, __shfl_xor_sync(0xffffffffu, mx, o));
    float sum = 0.0f;
#pragma unroll
    for (int i = 0; i < 32; i++) { vals[i] = __expf(vals[i] - mx); sum += vals[i]; }
#pragma unroll
    for (int o = 16; o; o >>= 1) sum += __shfl_xor_sync(0xffffffffu, sum, o);
    const float inv = 1.0f / sum;
#pragma unroll
    for (int i = 0; i < 32; i++) {
        const int c = lane + i * 32;
        prob[pb + c] = w0 * vals[i] * inv + l1 * g_relp[mrow + c];
    }
}

// ---------------------------------------------------------------------------
// Kernel 3: HMMA pv. out = prob @ V per (b,h). CTA 128q x 64hd, K-slab 64.
// ---------------------------------------------------------------------------
constexpr int PV_SMEM = 49152;

__global__ __launch_bounds__(256, 2)
void pv_mma_kernel(const float* __restrict__ prob, float* __restrict__ outp)
{
    extern __shared__ char sm3[];
    char* phi_s = sm3;
    char* plo_s = sm3 + 16384;
    char* vhi_s = sm3 + 32768;
    char* vlo_s = sm3 + 40960;
    const uint32_t uPhi = smem_to_u32(phi_s);
    const uint32_t uPlo = smem_to_u32(plo_s);
    const uint32_t uVhi = smem_to_u32(vhi_s);
    const uint32_t uVlo = smem_to_u32(vlo_s);

    const int tid  = threadIdx.x;
    const int warp = tid >> 5;
    const int lane = tid & 31;
    const int wm = warp >> 1;          // 0..3 (32 q rows)
    const int wn = warp & 1;           // 0..1 (32 hd cols)
    const int bh = blockIdx.y;
    const int b = bh / PH, h = bh % PH;
    const int q0 = blockIdx.x * 128;

    const size_t pbase = ((size_t)bh * PS + q0) * PS;
    const size_t vtb = (size_t)bh * PHD * PS;

    float acc[2][4][4];
#pragma unroll
    for (int i = 0; i < 2; i++)
#pragma unroll
        for (int j = 0; j < 4; j++)
#pragma unroll
            for (int c = 0; c < 4; c++) acc[i][j][c] = 0.0f;

    const int lrow  = lane & 15;
    const int lcolb = (lane >> 4) * 16;

    for (int kc0 = 0; kc0 < PS; kc0 += 64) {
        __syncthreads();
        // prob tile [128 q][64 k] fp32 -> bf16 hi/lo swizzled
#pragma unroll
        for (int it = 0; it < 8; it++) {
            const int c = tid + it * 256;          // 0..2047 float4 chunks
            const int q = c >> 4, k4 = (c & 15) * 4;
            const float4 v = *(const float4*)(prob + pbase + (size_t)q * PS + kc0 + k4);
            const __nv_bfloat16 h0 = __float2bfloat16_rn(v.x);
            const __nv_bfloat16 h1 = __float2bfloat16_rn(v.y);
            const __nv_bfloat16 h2 = __float2bfloat16_rn(v.z);
            const __nv_bfloat16 h3 = __float2bfloat16_rn(v.w);
            __nv_bfloat162 hp01 = __halves2bfloat162(h0, h1);
            __nv_bfloat162 hp23 = __halves2bfloat162(h2, h3);
            __nv_bfloat162 lp01 = __floats2bfloat162_rn(v.x - __bfloat162float(h0),
                                                        v.y - __bfloat162float(h1));
            __nv_bfloat162 lp23 = __floats2bfloat162_rn(v.z - __bfloat162float(h2),
                                                        v.w - __bfloat162float(h3));
            uint2 hv, lv;
            hv.x = *reinterpret_cast<uint32_t*>(&hp01);
            hv.y = *reinterpret_cast<uint32_t*>(&hp23);
            lv.x = *reinterpret_cast<uint32_t*>(&lp01);
            lv.y = *reinterpret_cast<uint32_t*>(&lp23);
            *(uint2*)(phi_s + SWZ128(q * 128 + k4 * 2)) = hv;
            *(uint2*)(plo_s + SWZ128(q * 128 + k4 * 2)) = lv;
        }
        // vT slab [64 hd][64 k]
#pragma unroll
        for (int it = 0; it < 2; it++) {
            const int c = tid + it * 256;          // 0..511 16B chunks
            const int r = c >> 3, e8 = (c & 7) * 8;
            *(uint4*)(vhi_s + SWZ128(r * 128 + e8 * 2)) =
                *(const uint4*)(g_vthi + vtb + (size_t)r * PS + kc0 + e8);
            *(uint4*)(vlo_s + SWZ128(r * 128 + e8 * 2)) =
                *(const uint4*)(g_vtlo + vtb + (size_t)r * PS + kc0 + e8);
        }
        __syncthreads();
#pragma unroll
        for (int ks = 0; ks < 4; ks++) {
            const int kb = ks * 32 + lcolb;
            uint32_t bhi[2][4], blo[2][4];
#pragma unroll
            for (int nt2 = 0; nt2 < 2; nt2++) {
                const int brow = wn * 32 + nt2 * 16 + lrow;
                ldmx4(bhi[nt2], uVhi + SWZ128(brow * 128 + kb));
                ldmx4(blo[nt2], uVlo + SWZ128(brow * 128 + kb));
            }
#pragma unroll
            for (int mt = 0; mt < 2; mt++) {
                const int arow = wm * 32 + mt * 16 + lrow;
                uint32_t a[4];
                ldmx4(a, uPhi + SWZ128(arow * 128 + kb));
#pragma unroll
                for (int nt2 = 0; nt2 < 2; nt2++)
#pragma unroll
                    for (int j = 0; j < 2; j++) {
                        mma16816(acc[mt][nt2 * 2 + j], a, bhi[nt2][j], bhi[nt2][2 + j]);
                        mma16816(acc[mt][nt2 * 2 + j], a, blo[nt2][j], blo[nt2][2 + j]);
                    }
                ldmx4(a, uPlo + SWZ128(arow * 128 + kb));
#pragma unroll
                for (int nt2 = 0; nt2 < 2; nt2++)
#pragma unroll
                    for (int j = 0; j < 2; j++)
                        mma16816(acc[mt][nt2 * 2 + j], a, bhi[nt2][j], bhi[nt2][2 + j]);
            }
        }
    }
    // epilogue
    const int g   = lane >> 2;
    const int tg2 = (lane & 3) * 2;
#pragma unroll
    for (int mt = 0; mt < 2; mt++) {
#pragma unroll
        for (int nt = 0; nt < 4; nt++) {
            const int nc = wn * 32 + nt * 8 + tg2;
            const int m = q0 + wm * 32 + mt * 16 + g;
            float2 v0, v1;
            v0.x = acc[mt][nt][0]; v0.y = acc[mt][nt][1];
            v1.x = acc[mt][nt][2]; v1.y = acc[mt][nt][3];
            *(float2*)(outp + ((size_t)b * PS + m) * PD + h * PHD + nc)     = v0;
            *(float2*)(outp + ((size_t)b * PS + m + 8) * PD + h * PHD + nc) = v1;
        }
    }
}

// ---------------------------------------------------------------------------
extern "C" void kernel_launch(void* const* d_in, const int* in_sizes, int n_in,
                              void* d_out, int out_size) {
    const float* query = (const float*)d_in[0];
    const float* key   = (const float*)d_in[1];
    const float* value = (const float*)d_in[2];
    const float* rel   = (const float*)d_in[3];
    const void*  mask  = d_in[4];
    const float* l1    = (const float*)d_in[5];
    const float* Wq    = (const float*)d_in[6];
    const float* bq    = (const float*)d_in[7];
    const float* Wk    = (const float*)d_in[8];
    const float* bk    = (const float*)d_in[9];
    const float* Wv    = (const float*)d_in[10];
    const float* bv    = (const float*)d_in[11];

    float* outp = (float*)d_out;
    float* prob = outp + OUT_ELEMS;

    detect_mask_kernel<<<1, 256>>>(mask);

    conv_x_kernel<<<dim3((unsigned)(XE / 512), 3), 256>>>(query, key, value);
    conv_w_kernel<<<dim3((unsigned)(WE / 512), 3), 256>>>(Wq, Wk, Wv);
    relp_kernel<<<1024, 256>>>(rel, mask);

    cudaFuncSetAttribute(proj_mma_kernel,
                         cudaFuncAttributeMaxDynamicSharedMemorySize, PROJ_SMEM);
    dim3 g1(PD / 128, (PB * PS) / 128, 3);     // (6, 64, 3)
    proj_mma_kernel<<<g1, 256, PROJ_SMEM>>>(bq, bk, bv);

    vtrans_kernel<<<dim3(16, PB * PH), 256>>>();

    cudaFuncSetAttribute(scores_gemm_kernel,
                         cudaFuncAttributeMaxDynamicSharedMemorySize, SG_SMEM);
    dim3 g2(PS / 128, PS / 128, PB * PH);      // (8, 8, 96)
    scores_gemm_kernel<<<g2, 256, SG_SMEM>>>(prob);

    softmax_combine_kernel<<<(PB * PH * PS) / 8, 256>>>(mask, l1, prob);

    cudaFuncSetAttribute(pv_mma_kernel,
                         cudaFuncAttributeMaxDynamicSharedMemorySize, PV_SMEM);
    dim3 g3(PS / 128, PB * PH);                // (8, 96)
    pv_mma_kernel<<<g3, 256, PV_SMEM>>>(prob, outp);
}

// round 12
// speedup vs baseline: 2.2201x; 1.1027x over previous
#include <cuda_runtime.h>
#include <cuda_bf16.h>
#include <cstdint>
#include <cstddef>

// Problem constants
constexpr int PB = 8, PS = 1024, PD = 768, PH = 12, PHD = 64;
constexpr size_t QKV_ELEMS = (size_t)PB * PH * PS * PHD;        // 6,291,456
constexpr size_t OUT_ELEMS = (size_t)PB * PS * PD;              // 6,291,456
constexpr size_t XE = (size_t)PB * PS * PD;                     // per matrix
constexpr size_t WE = (size_t)PD * PD;                          // per matrix
constexpr size_t RELP_ELEMS = (size_t)PB * PS * PS;             // 8,388,608

// Scratch (no allocations allowed -> __device__ globals)
__device__ __nv_bfloat16 g_xhi[3 * XE];
__device__ __nv_bfloat16 g_xlo[3 * XE];
__device__ __nv_bfloat16 g_whi[3 * WE];
__device__ __nv_bfloat16 g_wlo[3 * WE];
__device__ __nv_bfloat16 g_qhi[QKV_ELEMS], g_qlo[QKV_ELEMS];
__device__ __nv_bfloat16 g_khi[QKV_ELEMS], g_klo[QKV_ELEMS];
__device__ __nv_bfloat16 g_vhi[QKV_ELEMS], g_vlo[QKV_ELEMS];
__device__ __nv_bfloat16 g_vthi[QKV_ELEMS], g_vtlo[QKV_ELEMS];   // [b][h][hd][s]
__device__ float g_relp[RELP_ELEMS];
__device__ uint32_t g_maskbits[RELP_ELEMS / 32];                 // 1MB packed mask
__device__ int   g_mask_mode;   // 0 = uint8/bool, 1 = int32, 2 = float32

// ---------------------------------------------------------------------------
// Tensor-core helpers (portable sm_80+ path: ldmatrix + mma.sync bf16)
// ---------------------------------------------------------------------------
__device__ __forceinline__ uint32_t smem_to_u32(const void* p) {
    uint32_t a;
    asm("{ .reg .u64 t; cvta.to.shared.u64 t, %1; cvt.u32.u64 %0, t; }" : "=r"(a) : "l"(p));
    return a;
}
__device__ __forceinline__ void ldmx4(uint32_t* r, uint32_t addr) {
    asm volatile("ldmatrix.sync.aligned.m8n8.x4.shared.b16 {%0,%1,%2,%3}, [%4];"
        : "=r"(r[0]), "=r"(r[1]), "=r"(r[2]), "=r"(r[3]) : "r"(addr));
}
__device__ __forceinline__ void mma16816(float* c, const uint32_t* a, uint32_t b0, uint32_t b1) {
    asm volatile("mma.sync.aligned.m16n8k16.row.col.f32.bf16.bf16.f32 "
        "{%0,%1,%2,%3}, {%4,%5,%6,%7}, {%8,%9}, {%0,%1,%2,%3};"
        : "+f"(c[0]), "+f"(c[1]), "+f"(c[2]), "+f"(c[3])
        : "r"(a[0]), "r"(a[1]), "r"(a[2]), "r"(a[3]), "r"(b0), "r"(b1));
}
#define SWZ128(off) ((off) ^ (((off) >> 3) & 0x70))

// ---------------------------------------------------------------------------
// Mask dtype probe (deterministic)
// ---------------------------------------------------------------------------
__global__ void detect_mask_kernel(const void* __restrict__ mask) {
    __shared__ int sawFloat, sawOther;
    if (threadIdx.x == 0) { sawFloat = 0; sawOther = 0; }
    __syncthreads();
    const unsigned int* w = (const unsigned int*)mask;
    int lf = 0, lo = 0;
    for (int i = threadIdx.x; i < 2048; i += blockDim.x) {
        unsigned int x = w[i];
        if (x == 0x3F800000u) lf = 1;
        else if (x > 1u) lo = 1;
    }
    if (lf) atomicOr(&sawFloat, 1);
    if (lo) atomicOr(&sawOther, 1);
    __syncthreads();
    if (threadIdx.x == 0) g_mask_mode = sawFloat ? 2 : (sawOther ? 0 : 1);
}

__device__ __forceinline__ bool read_mask(const void* m, size_t idx, int mode) {
    if (mode == 0) return ((const unsigned char*)m)[idx] != 0;
    if (mode == 1) return ((const int*)m)[idx] != 0;
    return ((const float*)m)[idx] != 0.0f;
}

// ---------------------------------------------------------------------------
// Conversion kernels: fp32 -> (bf16 hi, bf16 lo) split
// ---------------------------------------------------------------------------
__global__ void conv_x_kernel(const float* __restrict__ q, const float* __restrict__ k,
                              const float* __restrict__ v) {
    const int z = blockIdx.y;
    const float* src = (z == 0) ? q : (z == 1) ? k : v;
    __nv_bfloat16* hi = g_xhi + (size_t)z * XE;
    __nv_bfloat16* lo = g_xlo + (size_t)z * XE;
    const size_t i2 = ((size_t)blockIdx.x * blockDim.x + threadIdx.x) * 2;
    if (i2 + 1 >= XE) return;
    const float2 s = *(const float2*)(src + i2);
    const __nv_bfloat16 h0 = __float2bfloat16_rn(s.x);
    const __nv_bfloat16 h1 = __float2bfloat16_rn(s.y);
    *(__nv_bfloat162*)(hi + i2) = __halves2bfloat162(h0, h1);
    *(__nv_bfloat162*)(lo + i2) = __floats2bfloat162_rn(
        s.x - __bfloat162float(h0), s.y - __bfloat162float(h1));
}

__global__ void conv_w_kernel(const float* __restrict__ wq, const float* __restrict__ wk,
                              const float* __restrict__ wv) {
    const int z = blockIdx.y;
    const float* src = (z == 0) ? wq : (z == 1) ? wk : wv;
    __nv_bfloat16* hi = g_whi + (size_t)z * WE;
    __nv_bfloat16* lo = g_wlo + (size_t)z * WE;
    const size_t i2 = ((size_t)blockIdx.x * blockDim.x + threadIdx.x) * 2;
    if (i2 + 1 >= WE) return;
    const float2 s = *(const float2*)(src + i2);
    const __nv_bfloat16 h0 = __float2bfloat16_rn(s.x);
    const __nv_bfloat16 h1 = __float2bfloat16_rn(s.y);
    *(__nv_bfloat162*)(hi + i2) = __halves2bfloat162(h0, h1);
    *(__nv_bfloat162*)(lo + i2) = __floats2bfloat162_rn(
        s.x - __bfloat162float(h0), s.y - __bfloat162float(h1));
}

// ---------------------------------------------------------------------------
// relp kernel: rel_attn softmax per row + pack mask to bitmask.
// Scalar layout c = lane + i*32 so __ballot gives word for cols [i*32,i*32+32).
// ---------------------------------------------------------------------------
__global__ void relp_kernel(const float* __restrict__ rel, const void* __restrict__ mask) {
    const int lane = threadIdx.x & 31;
    const int warp = threadIdx.x >> 5;
    const int row = blockIdx.x * 8 + warp;          // 0..8191 = b*1024+s
    const size_t rbase = (size_t)row * PS;
    const int mmode = g_mask_mode;
    float vals[32];
    uint32_t myword = 0;
    float mx = -3.0e38f;
#pragma unroll
    for (int i = 0; i < 32; i++) {
        const int c = lane + i * 32;
        const bool m = read_mask(mask, rbase + c, mmode);
        const uint32_t w = __ballot_sync(0xffffffffu, m);
        if (lane == i) myword = w;
        const float v = rel[rbase + c];
        const float relm = m ? v : 0.0f;
        const float logit = (relm == 0.0f) ? -10000.0f : relm;
        vals[i] = logit;
        mx = fmaxf(mx, logit);
    }
    g_maskbits[(size_t)row * 32 + lane] = myword;
#pragma unroll
    for (int o = 16; o; o >>= 1) mx = fmaxf(mx, __shfl_xor_sync(0xffffffffu, mx, o));
    float sum = 0.0f;
#pragma unroll
    for (int i = 0; i < 32; i++) { vals[i] = __expf(vals[i] - mx); sum += vals[i]; }
#pragma unroll
    for (int o = 16; o; o >>= 1) sum += __shfl_xor_sync(0xffffffffu, sum, o);
    const float inv = 1.0f / sum;
#pragma unroll
    for (int i = 0; i < 32; i++) g_relp[rbase + lane + i * 32] = vals[i] * inv;
}

// ---------------------------------------------------------------------------
// Kernel 1: HMMA bf16-split projection GEMM (emits bf16 hi/lo QKV).
// ---------------------------------------------------------------------------
constexpr int PROJ_SMEM = 4 * 16384;   // 64KB dynamic

__device__ __forceinline__ void load_slab_part(const __nv_bfloat16* __restrict__ src,
                                               int row0, int k0, char* dst, int tid) {
#pragma unroll
    for (int it = 0; it < 4; it++) {
        const int c = tid + it * 256;          // 0..1023 16B-chunks
        const int r = c >> 3;                  // 0..127
        const int e8 = (c & 7) * 8;            // bf16 element offset in row
        const uint4 v = *(const uint4*)(src + (size_t)(row0 + r) * PD + k0 + e8);
        *(uint4*)(dst + SWZ128(r * 128 + e8 * 2)) = v;
    }
}

// Load a [128 x 64] bf16 tile whose rows are contiguous 64-element (128B) rows.
__device__ __forceinline__ void load_tile64(const __nv_bfloat16* __restrict__ src,
                                            size_t base, char* dst, int tid) {
#pragma unroll
    for (int it = 0; it < 4; it++) {
        const int c = tid + it * 256;          // 0..1023 16B-chunks
        const int r = c >> 3;                  // 0..127
        const int e8 = (c & 7) * 8;
        const uint4 v = *(const uint4*)(src + base + (size_t)r * 64 + e8);
        *(uint4*)(dst + SWZ128(r * 128 + e8 * 2)) = v;
    }
}

__global__ __launch_bounds__(256, 2)
void proj_mma_kernel(const float* __restrict__ bq, const float* __restrict__ bk,
                     const float* __restrict__ bv)
{
    extern __shared__ char sm[];
    __shared__ float bias_s[128];

    const int tid  = threadIdx.x;
    const int warp = tid >> 5;
    const int lane = tid & 31;
    const int wm = warp >> 2;
    const int wn = warp & 3;
    const int z  = blockIdx.z;
    const int n0 = blockIdx.x * 128;
    const int m0 = blockIdx.y * 128;

    const __nv_bfloat16* xhi = g_xhi + (size_t)z * XE;
    const __nv_bfloat16* xlo = g_xlo + (size_t)z * XE;
    const __nv_bfloat16* whi = g_whi + (size_t)z * WE;
    const __nv_bfloat16* wlo = g_wlo + (size_t)z * WE;
    const float* bias = (z == 0) ? bq : (z == 1) ? bk : bv;
    __nv_bfloat16* ohi = (z == 0) ? g_qhi : (z == 1) ? g_khi : g_vhi;
    __nv_bfloat16* olo = (z == 0) ? g_qlo : (z == 1) ? g_klo : g_vlo;

    if (tid < 128) bias_s[tid] = bias[n0 + tid];

    char* Ahi_s = sm;
    char* Alo_s = sm + 16384;
    char* Bhi_s = sm + 32768;
    char* Blo_s = sm + 49152;
    const uint32_t uAhi = smem_to_u32(Ahi_s);
    const uint32_t uAlo = smem_to_u32(Alo_s);
    const uint32_t uBhi = smem_to_u32(Bhi_s);
    const uint32_t uBlo = smem_to_u32(Blo_s);

    float acc[4][4][4];
#pragma unroll
    for (int i = 0; i < 4; i++)
#pragma unroll
        for (int j = 0; j < 4; j++)
#pragma unroll
            for (int c = 0; c < 4; c++) acc[i][j][c] = 0.0f;

    const int lrow  = lane & 15;
    const int lcolb = (lane >> 4) * 16;

    for (int s = 0; s < 12; s++) {
        __syncthreads();
        const int k0 = s * 64;
        load_slab_part(xhi, m0, k0, Ahi_s, tid);
        load_slab_part(xlo, m0, k0, Alo_s, tid);
        load_slab_part(whi, n0, k0, Bhi_s, tid);
        load_slab_part(wlo, n0, k0, Blo_s, tid);
        __syncthreads();
#pragma unroll
        for (int ks = 0; ks < 4; ks++) {
            const int kb = ks * 32 + lcolb;
            uint32_t bhi[2][4], blo[2][4];
#pragma unroll
            for (int nt2 = 0; nt2 < 2; nt2++) {
                const int brow = wn * 32 + nt2 * 16 + lrow;
                ldmx4(bhi[nt2], uBhi + SWZ128(brow * 128 + kb));
                ldmx4(blo[nt2], uBlo + SWZ128(brow * 128 + kb));
            }
#pragma unroll
            for (int mt = 0; mt < 4; mt++) {
                const int arow = wm * 64 + mt * 16 + lrow;
                uint32_t a[4];
                ldmx4(a, uAhi + SWZ128(arow * 128 + kb));       // Ahi
#pragma unroll
                for (int nt2 = 0; nt2 < 2; nt2++)
#pragma unroll
                    for (int j = 0; j < 2; j++) {
                        mma16816(acc[mt][nt2 * 2 + j], a, bhi[nt2][j], bhi[nt2][2 + j]);
                        mma16816(acc[mt][nt2 * 2 + j], a, blo[nt2][j], blo[nt2][2 + j]);
                    }
                ldmx4(a, uAlo + SWZ128(arow * 128 + kb));       // Alo
#pragma unroll
                for (int nt2 = 0; nt2 < 2; nt2++)
#pragma unroll
                    for (int j = 0; j < 2; j++)
                        mma16816(acc[mt][nt2 * 2 + j], a, bhi[nt2][j], bhi[nt2][2 + j]);
            }
        }
    }

    // Epilogue: +bias, split to bf16 hi/lo, scatter [b][h][s][hd]
    const int g   = lane >> 2;
    const int tg2 = (lane & 3) * 2;
#pragma unroll
    for (int mt = 0; mt < 4; mt++) {
#pragma unroll
        for (int nt = 0; nt < 4; nt++) {
            const int nc = wn * 32 + nt * 8 + tg2;
            const int n = n0 + nc;
            const int h = n >> 6, hd = n & 63;
            const int m = m0 + wm * 64 + mt * 16 + g;
            const int b = m >> 10, sq = m & 1023;
#pragma unroll
            for (int cc = 0; cc < 2; cc++) {
                const float y0 = acc[mt][nt][cc * 2 + 0] + bias_s[nc];
                const float y1 = acc[mt][nt][cc * 2 + 1] + bias_s[nc + 1];
                const __nv_bfloat16 h0 = __float2bfloat16_rn(y0);
                const __nv_bfloat16 h1 = __float2bfloat16_rn(y1);
                const size_t di = (((size_t)(b * PH + h)) * PS + sq + cc * 8) * PHD + hd;
                *(__nv_bfloat162*)(ohi + di) = __halves2bfloat162(h0, h1);
                *(__nv_bfloat162*)(olo + di) = __floats2bfloat162_rn(
                    y0 - __bfloat162float(h0), y1 - __bfloat162float(h1));
            }
        }
    }
}

// ---------------------------------------------------------------------------
// V transpose: [b][h][s][hd] -> [b][h][hd][s] (hi and lo)
// ---------------------------------------------------------------------------
__global__ void vtrans_kernel() {
    __shared__ __nv_bfloat16 th[64][65], tl[64][65];
    const int tid = threadIdx.x;
    const int bh = blockIdx.y;
    const int st = blockIdx.x * 64;
    const size_t src0 = ((size_t)bh * PS + st) * PHD;
#pragma unroll
    for (int it = 0; it < 16; it++) {
        const int i = tid + it * 256;
        const int s = i >> 6, hd = i & 63;
        th[hd][s] = g_vhi[src0 + (size_t)s * PHD + hd];
        tl[hd][s] = g_vlo[src0 + (size_t)s * PHD + hd];
    }
    __syncthreads();
    const size_t dst0 = (size_t)bh * PHD * PS + st;
#pragma unroll
    for (int it = 0; it < 16; it++) {
        const int i = tid + it * 256;
        const int hd = i >> 6, s = i & 63;
        g_vthi[dst0 + (size_t)hd * PS + s] = th[hd][s];
        g_vtlo[dst0 + (size_t)hd * PS + s] = tl[hd][s];
    }
}

// ---------------------------------------------------------------------------
// Kernel 2a: scores GEMM. Per CTA: 128 q x 128 k for one (b,h). Contraction
// dim = 64 (single slab). Writes RAW scores/8 (no mask) to prob.
// ---------------------------------------------------------------------------
constexpr int SG_SMEM = 4 * 16384;

__global__ __launch_bounds__(256, 2)
void scores_gemm_kernel(float* __restrict__ prob)
{
    extern __shared__ char sm4[];
    char* Qhi_s = sm4;
    char* Qlo_s = sm4 + 16384;
    char* Khi_s = sm4 + 32768;
    char* Klo_s = sm4 + 49152;
    const uint32_t uQhi = smem_to_u32(Qhi_s);
    const uint32_t uQlo = smem_to_u32(Qlo_s);
    const uint32_t uKhi = smem_to_u32(Khi_s);
    const uint32_t uKlo = smem_to_u32(Klo_s);

    const int tid  = threadIdx.x;
    const int warp = tid >> 5;
    const int lane = tid & 31;
    const int wm = warp >> 2;      // 0..1 -> 64 q-rows
    const int wn = warp & 3;       // 0..3 -> 32 k-cols
    const int bh = blockIdx.z;
    const int q0 = blockIdx.y * 128;
    const int k0 = blockIdx.x * 128;

    const size_t qb = ((size_t)bh * PS + q0) * PHD;
    const size_t kb0 = ((size_t)bh * PS + k0) * PHD;

    load_tile64(g_qhi, qb, Qhi_s, tid);
    load_tile64(g_qlo, qb, Qlo_s, tid);
    load_tile64(g_khi, kb0, Khi_s, tid);
    load_tile64(g_klo, kb0, Klo_s, tid);
    __syncthreads();

    float acc[4][4][4];
#pragma unroll
    for (int i = 0; i < 4; i++)
#pragma unroll
        for (int j = 0; j < 4; j++)
#pragma unroll
            for (int c = 0; c < 4; c++) acc[i][j][c] = 0.0f;

    const int lrow  = lane & 15;
    const int lcolb = (lane >> 4) * 16;

#pragma unroll
    for (int ks = 0; ks < 4; ks++) {
        const int kb = ks * 32 + lcolb;
        uint32_t bhi[2][4], blo[2][4];
#pragma unroll
        for (int nt2 = 0; nt2 < 2; nt2++) {
            const int brow = wn * 32 + nt2 * 16 + lrow;
            ldmx4(bhi[nt2], uKhi + SWZ128(brow * 128 + kb));
            ldmx4(blo[nt2], uKlo + SWZ128(brow * 128 + kb));
        }
#pragma unroll
        for (int mt = 0; mt < 4; mt++) {
            const int arow = wm * 64 + mt * 16 + lrow;
            uint32_t a[4];
            ldmx4(a, uQhi + SWZ128(arow * 128 + kb));       // Qhi
#pragma unroll
            for (int nt2 = 0; nt2 < 2; nt2++)
#pragma unroll
                for (int j = 0; j < 2; j++) {
                    mma16816(acc[mt][nt2 * 2 + j], a, bhi[nt2][j], bhi[nt2][2 + j]);
                    mma16816(acc[mt][nt2 * 2 + j], a, blo[nt2][j], blo[nt2][2 + j]);
                }
            ldmx4(a, uQlo + SWZ128(arow * 128 + kb));       // Qlo
#pragma unroll
            for (int nt2 = 0; nt2 < 2; nt2++)
#pragma unroll
                for (int j = 0; j < 2; j++)
                    mma16816(acc[mt][nt2 * 2 + j], a, bhi[nt2][j], bhi[nt2][2 + j]);
        }
    }

    // Epilogue: scale by 1/8, write to prob[(bh*PS+q)*PS + k]
    const int g   = lane >> 2;
    const int tg2 = (lane & 3) * 2;
    const size_t pb = (size_t)bh * PS * PS;
#pragma unroll
    for (int mt = 0; mt < 4; mt++) {
#pragma unroll
        for (int nt = 0; nt < 4; nt++) {
            const int kcol = k0 + wn * 32 + nt * 8 + tg2;
            const int qr = q0 + wm * 64 + mt * 16 + g;
            float2 v0, v1;
            v0.x = acc[mt][nt][0] * 0.125f; v0.y = acc[mt][nt][1] * 0.125f;
            v1.x = acc[mt][nt][2] * 0.125f; v1.y = acc[mt][nt][3] * 0.125f;
            *(float2*)(prob + pb + (size_t)qr * PS + kcol)       = v0;
            *(float2*)(prob + pb + (size_t)(qr + 8) * PS + kcol) = v1;
        }
    }
}

// ---------------------------------------------------------------------------
// Kernel 2b: softmax + combine, one warp per (b,h,row). float4 loads,
// mask from packed bitmask (L2-resident), relp from L2-resident table.
// col = j*128 + lane*4 + e; word = j*4 + (lane>>3); bit = (lane&7)*4 + e.
// ---------------------------------------------------------------------------
__global__ void softmax_combine_kernel(const float* __restrict__ l1p,
                                       float* __restrict__ prob)
{
    const int lane = threadIdx.x & 31;
    const int warp = threadIdx.x >> 5;
    const int gid = blockIdx.x * 8 + warp;          // 0..98303 = bh*1024 + r
    const int bh = gid >> 10, r = gid & 1023;
    const int b = bh / PH;
    const size_t pb = (size_t)gid * PS;
    const size_t mrow = (size_t)b * PS + r;         // row idx into maskbits/relp
    const float l1 = *l1p;
    const float w0 = 1.0f - l1;

    const uint32_t myword = g_maskbits[mrow * 32 + lane];
    const int bitbase = (lane & 7) * 4;

    float4 vals[8];
    float mx = -3.0e38f;
#pragma unroll
    for (int j = 0; j < 8; j++) {
        const int col = j * 128 + lane * 4;
        float4 s = *(const float4*)(prob + pb + col);
        const uint32_t w = __shfl_sync(0xffffffffu, myword, j * 4 + (lane >> 3));
        s.x = ((w >> (bitbase + 0)) & 1u) ? -1.0e9f : s.x;
        s.y = ((w >> (bitbase + 1)) & 1u) ? -1.0e9f : s.y;
        s.z = ((w >> (bitbase + 2)) & 1u) ? -1.0e9f : s.z;
        s.w = ((w >> (bitbase + 3)) & 1u) ? -1.0e9f : s.w;
        vals[j] = s;
        mx = fmaxf(mx, fmaxf(fmaxf(s.x, s.y), fmaxf(s.z, s.w)));
    }
#pragma unroll
    for (int o = 16; o; o >>= 1) mx = fmaxf(mx, __shfl_xor_sync(0xffffffffu, mx, o));
    float sum = 0.0f;
#pragma unroll
    for (int j = 0; j < 8; j++) {
        vals[j].x = __expf(vals[j].x - mx);
        vals[j].y = __expf(vals[j].y - mx);
        vals[j].z = __expf(vals[j].z - mx);
        vals[j].w = __expf(vals[j].w - mx);
        sum += vals[j].x + vals[j].y + vals[j].z + vals[j].w;
    }
#pragma unroll
    for (int o = 16; o; o >>= 1) sum += __shfl_xor_sync(0xffffffffu, sum, o);
    const float winv = w0 / sum;
    const float* rp = g_relp + mrow * PS;
#pragma unroll
    for (int j = 0; j < 8; j++) {
        const int col = j * 128 + lane * 4;
        const float4 rv = *(const float4*)(rp + col);
        float4 o;
        o.x = vals[j].x * winv + l1 * rv.x;
        o.y = vals[j].y * winv + l1 * rv.y;
        o.z = vals[j].z * winv + l1 * rv.z;
        o.w = vals[j].w * winv + l1 * rv.w;
        *(float4*)(prob + pb + col) = o;
    }
}

// ---------------------------------------------------------------------------
// Kernel 3: HMMA pv. out = prob @ V per (b,h). CTA 128q x 64hd, K-slab 64.
// ---------------------------------------------------------------------------
constexpr int PV_SMEM = 49152;

__global__ __launch_bounds__(256, 2)
void pv_mma_kernel(const float* __restrict__ prob, float* __restrict__ outp)
{
    extern __shared__ char sm3[];
    char* phi_s = sm3;
    char* plo_s = sm3 + 16384;
    char* vhi_s = sm3 + 32768;
    char* vlo_s = sm3 + 40960;
    const uint32_t uPhi = smem_to_u32(phi_s);
    const uint32_t uPlo = smem_to_u32(plo_s);
    const uint32_t uVhi = smem_to_u32(vhi_s);
    const uint32_t uVlo = smem_to_u32(vlo_s);

    const int tid  = threadIdx.x;
    const int warp = tid >> 5;
    const int lane = tid & 31;
    const int wm = warp >> 1;          // 0..3 (32 q rows)
    const int wn = warp & 1;           // 0..1 (32 hd cols)
    const int bh = blockIdx.y;
    const int b = bh / PH, h = bh % PH;
    const int q0 = blockIdx.x * 128;

    const size_t pbase = ((size_t)bh * PS + q0) * PS;
    const size_t vtb = (size_t)bh * PHD * PS;

    float acc[2][4][4];
#pragma unroll
    for (int i = 0; i < 2; i++)
#pragma unroll
        for (int j = 0; j < 4; j++)
#pragma unroll
            for (int c = 0; c < 4; c++) acc[i][j][c] = 0.0f;

    const int lrow  = lane & 15;
    const int lcolb = (lane >> 4) * 16;

    for (int kc0 = 0; kc0 < PS; kc0 += 64) {
        __syncthreads();
        // prob tile [128 q][64 k] fp32 -> bf16 hi/lo swizzled
#pragma unroll
        for (int it = 0; it < 8; it++) {
            const int c = tid + it * 256;          // 0..2047 float4 chunks
            const int q = c >> 4, k4 = (c & 15) * 4;
            const float4 v = *(const float4*)(prob + pbase + (size_t)q * PS + kc0 + k4);
            const __nv_bfloat16 h0 = __float2bfloat16_rn(v.x);
            const __nv_bfloat16 h1 = __float2bfloat16_rn(v.y);
            const __nv_bfloat16 h2 = __float2bfloat16_rn(v.z);
            const __nv_bfloat16 h3 = __float2bfloat16_rn(v.w);
            __nv_bfloat162 hp01 = __halves2bfloat162(h0, h1);
            __nv_bfloat162 hp23 = __halves2bfloat162(h2, h3);
            __nv_bfloat162 lp01 = __floats2bfloat162_rn(v.x - __bfloat162float(h0),
                                                        v.y - __bfloat162float(h1));
            __nv_bfloat162 lp23 = __floats2bfloat162_rn(v.z - __bfloat162float(h2),
                                                        v.w - __bfloat162float(h3));
            uint2 hv, lv;
            hv.x = *reinterpret_cast<uint32_t*>(&hp01);
            hv.y = *reinterpret_cast<uint32_t*>(&hp23);
            lv.x = *reinterpret_cast<uint32_t*>(&lp01);
            lv.y = *reinterpret_cast<uint32_t*>(&lp23);
            *(uint2*)(phi_s + SWZ128(q * 128 + k4 * 2)) = hv;
            *(uint2*)(plo_s + SWZ128(q * 128 + k4 * 2)) = lv;
        }
        // vT slab [64 hd][64 k]
#pragma unroll
        for (int it = 0; it < 2; it++) {
            const int c = tid + it * 256;          // 0..511 16B chunks
            const int r = c >> 3, e8 = (c & 7) * 8;
            *(uint4*)(vhi_s + SWZ128(r * 128 + e8 * 2)) =
                *(const uint4*)(g_vthi + vtb + (size_t)r * PS + kc0 + e8);
            *(uint4*)(vlo_s + SWZ128(r * 128 + e8 * 2)) =
                *(const uint4*)(g_vtlo + vtb + (size_t)r * PS + kc0 + e8);
        }
        __syncthreads();
#pragma unroll
        for (int ks = 0; ks < 4; ks++) {
            const int kb = ks * 32 + lcolb;
            uint32_t bhi[2][4], blo[2][4];
#pragma unroll
            for (int nt2 = 0; nt2 < 2; nt2++) {
                const int brow = wn * 32 + nt2 * 16 + lrow;
                ldmx4(bhi[nt2], uVhi + SWZ128(brow * 128 + kb));
                ldmx4(blo[nt2], uVlo + SWZ128(brow * 128 + kb));
            }
#pragma unroll
            for (int mt = 0; mt < 2; mt++) {
                const int arow = wm * 32 + mt * 16 + lrow;
                uint32_t a[4];
                ldmx4(a, uPhi + SWZ128(arow * 128 + kb));
#pragma unroll
                for (int nt2 = 0; nt2 < 2; nt2++)
#pragma unroll
                    for (int j = 0; j < 2; j++) {
                        mma16816(acc[mt][nt2 * 2 + j], a, bhi[nt2][j], bhi[nt2][2 + j]);
                        mma16816(acc[mt][nt2 * 2 + j], a, blo[nt2][j], blo[nt2][2 + j]);
                    }
                ldmx4(a, uPlo + SWZ128(arow * 128 + kb));
#pragma unroll
                for (int nt2 = 0; nt2 < 2; nt2++)
#pragma unroll
                    for (int j = 0; j < 2; j++)
                        mma16816(acc[mt][nt2 * 2 + j], a, bhi[nt2][j], bhi[nt2][2 + j]);
            }
        }
    }
    // epilogue
    const int g   = lane >> 2;
    const int tg2 = (lane & 3) * 2;
#pragma unroll
    for (int mt = 0; mt < 2; mt++) {
#pragma unroll
        for (int nt = 0; nt < 4; nt++) {
            const int nc = wn * 32 + nt * 8 + tg2;
            const int m = q0 + wm * 32 + mt * 16 + g;
            float2 v0, v1;
            v0.x = acc[mt][nt][0]; v0.y = acc[mt][nt][1];
            v1.x = acc[mt][nt][2]; v1.y = acc[mt][nt][3];
            *(float2*)(outp + ((size_t)b * PS + m) * PD + h * PHD + nc)     = v0;
            *(float2*)(outp + ((size_t)b * PS + m + 8) * PD + h * PHD + nc) = v1;
        }
    }
}

// ---------------------------------------------------------------------------
extern "C" void kernel_launch(void* const* d_in, const int* in_sizes, int n_in,
                              void* d_out, int out_size) {
    const float* query = (const float*)d_in[0];
    const float* key   = (const float*)d_in[1];
    const float* value = (const float*)d_in[2];
    const float* rel   = (const float*)d_in[3];
    const void*  mask  = d_in[4];
    const float* l1    = (const float*)d_in[5];
    const float* Wq    = (const float*)d_in[6];
    const float* bq    = (const float*)d_in[7];
    const float* Wk    = (const float*)d_in[8];
    const float* bk    = (const float*)d_in[9];
    const float* Wv    = (const float*)d_in[10];
    const float* bv    = (const float*)d_in[11];

    float* outp = (float*)d_out;
    float* prob = outp + OUT_ELEMS;

    detect_mask_kernel<<<1, 256>>>(mask);

    conv_x_kernel<<<dim3((unsigned)(XE / 512), 3), 256>>>(query, key, value);
    conv_w_kernel<<<dim3((unsigned)(WE / 512), 3), 256>>>(Wq, Wk, Wv);
    relp_kernel<<<1024, 256>>>(rel, mask);

    cudaFuncSetAttribute(proj_mma_kernel,
                         cudaFuncAttributeMaxDynamicSharedMemorySize, PROJ_SMEM);
    dim3 g1(PD / 128, (PB * PS) / 128, 3);     // (6, 64, 3)
    proj_mma_kernel<<<g1, 256, PROJ_SMEM>>>(bq, bk, bv);

    vtrans_kernel<<<dim3(16, PB * PH), 256>>>();

    cudaFuncSetAttribute(scores_gemm_kernel,
                         cudaFuncAttributeMaxDynamicSharedMemorySize, SG_SMEM);
    dim3 g2(PS / 128, PS / 128, PB * PH);      // (8, 8, 96)
    scores_gemm_kernel<<<g2, 256, SG_SMEM>>>(prob);

    softmax_combine_kernel<<<(PB * PH * PS) / 8, 256>>>(l1, prob);

    cudaFuncSetAttribute(pv_mma_kernel,
                         cudaFuncAttributeMaxDynamicSharedMemorySize, PV_SMEM);
    dim3 g3(PS / 128, PB * PH);                // (8, 96)
    pv_mma_kernel<<<g3, 256, PV_SMEM>>>(prob, outp);
}

// round 13
// speedup vs baseline: 2.2392x; 1.0086x over previous
#include <cuda_runtime.h>
#include <cuda_bf16.h>
#include <cstdint>
#include <cstddef>

// Problem constants
constexpr int PB = 8, PS = 1024, PD = 768, PH = 12, PHD = 64;
constexpr size_t QKV_ELEMS = (size_t)PB * PH * PS * PHD;        // 6,291,456
constexpr size_t OUT_ELEMS = (size_t)PB * PS * PD;              // 6,291,456
constexpr size_t XE = (size_t)PB * PS * PD;                     // per matrix
constexpr size_t WE = (size_t)PD * PD;                          // per matrix
constexpr size_t RELP_ELEMS = (size_t)PB * PS * PS;             // 8,388,608

// Scratch (no allocations allowed -> __device__ globals)
__device__ __nv_bfloat16 g_xhi[3 * XE];
__device__ __nv_bfloat16 g_xlo[3 * XE];
__device__ __nv_bfloat16 g_whi[3 * WE];
__device__ __nv_bfloat16 g_wlo[3 * WE];
__device__ __nv_bfloat16 g_qhi[QKV_ELEMS], g_qlo[QKV_ELEMS];
__device__ __nv_bfloat16 g_khi[QKV_ELEMS], g_klo[QKV_ELEMS];
__device__ __nv_bfloat16 g_vhi[QKV_ELEMS], g_vlo[QKV_ELEMS];
__device__ __nv_bfloat16 g_vthi[QKV_ELEMS], g_vtlo[QKV_ELEMS];   // [b][h][hd][s]
__device__ float g_relp[RELP_ELEMS];
__device__ uint32_t g_maskbits[RELP_ELEMS / 32];                 // 1MB packed mask
__device__ int   g_mask_mode;   // 0 = uint8/bool, 1 = int32, 2 = float32

// ---------------------------------------------------------------------------
// Tensor-core + async-copy helpers
// ---------------------------------------------------------------------------
__device__ __forceinline__ uint32_t smem_to_u32(const void* p) {
    uint32_t a;
    asm("{ .reg .u64 t; cvta.to.shared.u64 t, %1; cvt.u32.u64 %0, t; }" : "=r"(a) : "l"(p));
    return a;
}
__device__ __forceinline__ void ldmx4(uint32_t* r, uint32_t addr) {
    asm volatile("ldmatrix.sync.aligned.m8n8.x4.shared.b16 {%0,%1,%2,%3}, [%4];"
        : "=r"(r[0]), "=r"(r[1]), "=r"(r[2]), "=r"(r[3]) : "r"(addr));
}
__device__ __forceinline__ void mma16816(float* c, const uint32_t* a, uint32_t b0, uint32_t b1) {
    asm volatile("mma.sync.aligned.m16n8k16.row.col.f32.bf16.bf16.f32 "
        "{%0,%1,%2,%3}, {%4,%5,%6,%7}, {%8,%9}, {%0,%1,%2,%3};"
        : "+f"(c[0]), "+f"(c[1]), "+f"(c[2]), "+f"(c[3])
        : "r"(a[0]), "r"(a[1]), "r"(a[2]), "r"(a[3]), "r"(b0), "r"(b1));
}
__device__ __forceinline__ void cp_async16(uint32_t dst, const void* src) {
    asm volatile("cp.async.cg.shared.global [%0], [%1], 16;" :: "r"(dst), "l"(src));
}
__device__ __forceinline__ void cp_commit() {
    asm volatile("cp.async.commit_group;" ::: "memory");
}
template <int N>
__device__ __forceinline__ void cp_wait() {
    asm volatile("cp.async.wait_group %0;" :: "n"(N) : "memory");
}
#define SWZ128(off) ((off) ^ (((off) >> 3) & 0x70))

// ---------------------------------------------------------------------------
// Mask dtype probe (deterministic)
// ---------------------------------------------------------------------------
__global__ void detect_mask_kernel(const void* __restrict__ mask) {
    __shared__ int sawFloat, sawOther;
    if (threadIdx.x == 0) { sawFloat = 0; sawOther = 0; }
    __syncthreads();
    const unsigned int* w = (const unsigned int*)mask;
    int lf = 0, lo = 0;
    for (int i = threadIdx.x; i < 2048; i += blockDim.x) {
        unsigned int x = w[i];
        if (x == 0x3F800000u) lf = 1;
        else if (x > 1u) lo = 1;
    }
    if (lf) atomicOr(&sawFloat, 1);
    if (lo) atomicOr(&sawOther, 1);
    __syncthreads();
    if (threadIdx.x == 0) g_mask_mode = sawFloat ? 2 : (sawOther ? 0 : 1);
}

__device__ __forceinline__ bool read_mask(const void* m, size_t idx, int mode) {
    if (mode == 0) return ((const unsigned char*)m)[idx] != 0;
    if (mode == 1) return ((const int*)m)[idx] != 0;
    return ((const float*)m)[idx] != 0.0f;
}

// ---------------------------------------------------------------------------
// Conversion kernels: fp32 -> (bf16 hi, bf16 lo) split
// ---------------------------------------------------------------------------
__global__ void conv_x_kernel(const float* __restrict__ q, const float* __restrict__ k,
                              const float* __restrict__ v) {
    const int z = blockIdx.y;
    const float* src = (z == 0) ? q : (z == 1) ? k : v;
    __nv_bfloat16* hi = g_xhi + (size_t)z * XE;
    __nv_bfloat16* lo = g_xlo + (size_t)z * XE;
    const size_t i2 = ((size_t)blockIdx.x * blockDim.x + threadIdx.x) * 2;
    if (i2 + 1 >= XE) return;
    const float2 s = *(const float2*)(src + i2);
    const __nv_bfloat16 h0 = __float2bfloat16_rn(s.x);
    const __nv_bfloat16 h1 = __float2bfloat16_rn(s.y);
    *(__nv_bfloat162*)(hi + i2) = __halves2bfloat162(h0, h1);
    *(__nv_bfloat162*)(lo + i2) = __floats2bfloat162_rn(
        s.x - __bfloat162float(h0), s.y - __bfloat162float(h1));
}

__global__ void conv_w_kernel(const float* __restrict__ wq, const float* __restrict__ wk,
                              const float* __restrict__ wv) {
    const int z = blockIdx.y;
    const float* src = (z == 0) ? wq : (z == 1) ? wk : wv;
    __nv_bfloat16* hi = g_whi + (size_t)z * WE;
    __nv_bfloat16* lo = g_wlo + (size_t)z * WE;
    const size_t i2 = ((size_t)blockIdx.x * blockDim.x + threadIdx.x) * 2;
    if (i2 + 1 >= WE) return;
    const float2 s = *(const float2*)(src + i2);
    const __nv_bfloat16 h0 = __float2bfloat16_rn(s.x);
    const __nv_bfloat16 h1 = __float2bfloat16_rn(s.y);
    *(__nv_bfloat162*)(hi + i2) = __halves2bfloat162(h0, h1);
    *(__nv_bfloat162*)(lo + i2) = __floats2bfloat162_rn(
        s.x - __bfloat162float(h0), s.y - __bfloat162float(h1));
}

// ---------------------------------------------------------------------------
// relp kernel: rel_attn softmax per row + pack mask to bitmask.
// ---------------------------------------------------------------------------
__global__ void relp_kernel(const float* __restrict__ rel, const void* __restrict__ mask) {
    const int lane = threadIdx.x & 31;
    const int warp = threadIdx.x >> 5;
    const int row = blockIdx.x * 8 + warp;          // 0..8191 = b*1024+s
    const size_t rbase = (size_t)row * PS;
    const int mmode = g_mask_mode;
    float vals[32];
    uint32_t myword = 0;
    float mx = -3.0e38f;
#pragma unroll
    for (int i = 0; i < 32; i++) {
        const int c = lane + i * 32;
        const bool m = read_mask(mask, rbase + c, mmode);
        const uint32_t w = __ballot_sync(0xffffffffu, m);
        if (lane == i) myword = w;
        const float v = rel[rbase + c];
        const float relm = m ? v : 0.0f;
        const float logit = (relm == 0.0f) ? -10000.0f : relm;
        vals[i] = logit;
        mx = fmaxf(mx, logit);
    }
    g_maskbits[(size_t)row * 32 + lane] = myword;
#pragma unroll
    for (int o = 16; o; o >>= 1) mx = fmaxf(mx, __shfl_xor_sync(0xffffffffu, mx, o));
    float sum = 0.0f;
#pragma unroll
    for (int i = 0; i < 32; i++) { vals[i] = __expf(vals[i] - mx); sum += vals[i]; }
#pragma unroll
    for (int o = 16; o; o >>= 1) sum += __shfl_xor_sync(0xffffffffu, sum, o);
    const float inv = 1.0f / sum;
#pragma unroll
    for (int i = 0; i < 32; i++) g_relp[rbase + lane + i * 32] = vals[i] * inv;
}

// ---------------------------------------------------------------------------
// Kernel 1: HMMA bf16-split projection GEMM, cp.async 2-stage pipeline.
// smem: stage p at p*65536: Ahi(16K) Alo Bhi Blo. Total 128KB, occ 1.
// ---------------------------------------------------------------------------
constexpr int PROJ_SMEM = 2 * 65536;

__device__ __forceinline__ void load_slab_async(const __nv_bfloat16* __restrict__ src,
                                                int row0, int k0, uint32_t dstu, int tid) {
#pragma unroll
    for (int it = 0; it < 4; it++) {
        const int c = tid + it * 256;          // 0..1023 16B-chunks
        const int r = c >> 3;                  // 0..127
        const int e8 = (c & 7) * 8;
        cp_async16(dstu + SWZ128(r * 128 + e8 * 2),
                   src + (size_t)(row0 + r) * PD + k0 + e8);
    }
}

// Load a [128 x 64] bf16 tile with contiguous 128B rows.
__device__ __forceinline__ void load_tile64(const __nv_bfloat16* __restrict__ src,
                                            size_t base, char* dst, int tid) {
#pragma unroll
    for (int it = 0; it < 4; it++) {
        const int c = tid + it * 256;
        const int r = c >> 3;
        const int e8 = (c & 7) * 8;
        const uint4 v = *(const uint4*)(src + base + (size_t)r * 64 + e8);
        *(uint4*)(dst + SWZ128(r * 128 + e8 * 2)) = v;
    }
}

__global__ __launch_bounds__(256, 1)
void proj_mma_kernel(const float* __restrict__ bq, const float* __restrict__ bk,
                     const float* __restrict__ bv)
{
    extern __shared__ char sm[];
    __shared__ float bias_s[128];

    const int tid  = threadIdx.x;
    const int warp = tid >> 5;
    const int lane = tid & 31;
    const int wm = warp >> 2;
    const int wn = warp & 3;
    const int z  = blockIdx.z;
    const int n0 = blockIdx.x * 128;
    const int m0 = blockIdx.y * 128;

    const __nv_bfloat16* xhi = g_xhi + (size_t)z * XE;
    const __nv_bfloat16* xlo = g_xlo + (size_t)z * XE;
    const __nv_bfloat16* whi = g_whi + (size_t)z * WE;
    const __nv_bfloat16* wlo = g_wlo + (size_t)z * WE;
    const float* bias = (z == 0) ? bq : (z == 1) ? bk : bv;
    __nv_bfloat16* ohi = (z == 0) ? g_qhi : (z == 1) ? g_khi : g_vhi;
    __nv_bfloat16* olo = (z == 0) ? g_qlo : (z == 1) ? g_klo : g_vlo;

    if (tid < 128) bias_s[tid] = bias[n0 + tid];

    const uint32_t ubase = smem_to_u32(sm);

    float acc[4][4][4];
#pragma unroll
    for (int i = 0; i < 4; i++)
#pragma unroll
        for (int j = 0; j < 4; j++)
#pragma unroll
            for (int c = 0; c < 4; c++) acc[i][j][c] = 0.0f;

    const int lrow  = lane & 15;
    const int lcolb = (lane >> 4) * 16;

    // prologue: slab 0 -> stage 0
    {
        const uint32_t du = ubase;
        load_slab_async(xhi, m0, 0, du,         tid);
        load_slab_async(xlo, m0, 0, du + 16384, tid);
        load_slab_async(whi, n0, 0, du + 32768, tid);
        load_slab_async(wlo, n0, 0, du + 49152, tid);
        cp_commit();
    }

    for (int s = 0; s < 12; s++) {
        if (s + 1 < 12) {
            const uint32_t du = ubase + ((s + 1) & 1) * 65536;
            const int k0 = (s + 1) * 64;
            load_slab_async(xhi, m0, k0, du,         tid);
            load_slab_async(xlo, m0, k0, du + 16384, tid);
            load_slab_async(whi, n0, k0, du + 32768, tid);
            load_slab_async(wlo, n0, k0, du + 49152, tid);
            cp_commit();
            cp_wait<1>();
        } else {
            cp_wait<0>();
        }
        __syncthreads();

        const uint32_t uAhi = ubase + (s & 1) * 65536;
        const uint32_t uAlo = uAhi + 16384;
        const uint32_t uBhi = uAhi + 32768;
        const uint32_t uBlo = uAhi + 49152;
#pragma unroll
        for (int ks = 0; ks < 4; ks++) {
            const int kb = ks * 32 + lcolb;
            uint32_t bhi[2][4], blo[2][4];
#pragma unroll
            for (int nt2 = 0; nt2 < 2; nt2++) {
                const int brow = wn * 32 + nt2 * 16 + lrow;
                ldmx4(bhi[nt2], uBhi + SWZ128(brow * 128 + kb));
                ldmx4(blo[nt2], uBlo + SWZ128(brow * 128 + kb));
            }
#pragma unroll
            for (int mt = 0; mt < 4; mt++) {
                const int arow = wm * 64 + mt * 16 + lrow;
                uint32_t a[4];
                ldmx4(a, uAhi + SWZ128(arow * 128 + kb));       // Ahi
#pragma unroll
                for (int nt2 = 0; nt2 < 2; nt2++)
#pragma unroll
                    for (int j = 0; j < 2; j++) {
                        mma16816(acc[mt][nt2 * 2 + j], a, bhi[nt2][j], bhi[nt2][2 + j]);
                        mma16816(acc[mt][nt2 * 2 + j], a, blo[nt2][j], blo[nt2][2 + j]);
                    }
                ldmx4(a, uAlo + SWZ128(arow * 128 + kb));       // Alo
#pragma unroll
                for (int nt2 = 0; nt2 < 2; nt2++)
#pragma unroll
                    for (int j = 0; j < 2; j++)
                        mma16816(acc[mt][nt2 * 2 + j], a, bhi[nt2][j], bhi[nt2][2 + j]);
            }
        }
        __syncthreads();   // buffer (s&1) free before it is refilled at s+2
    }

    // Epilogue: +bias, split to bf16 hi/lo, scatter [b][h][s][hd]
    const int g   = lane >> 2;
    const int tg2 = (lane & 3) * 2;
#pragma unroll
    for (int mt = 0; mt < 4; mt++) {
#pragma unroll
        for (int nt = 0; nt < 4; nt++) {
            const int nc = wn * 32 + nt * 8 + tg2;
            const int n = n0 + nc;
            const int h = n >> 6, hd = n & 63;
            const int m = m0 + wm * 64 + mt * 16 + g;
            const int b = m >> 10, sq = m & 1023;
#pragma unroll
            for (int cc = 0; cc < 2; cc++) {
                const float y0 = acc[mt][nt][cc * 2 + 0] + bias_s[nc];
                const float y1 = acc[mt][nt][cc * 2 + 1] + bias_s[nc + 1];
                const __nv_bfloat16 h0 = __float2bfloat16_rn(y0);
                const __nv_bfloat16 h1 = __float2bfloat16_rn(y1);
                const size_t di = (((size_t)(b * PH + h)) * PS + sq + cc * 8) * PHD + hd;
                *(__nv_bfloat162*)(ohi + di) = __halves2bfloat162(h0, h1);
                *(__nv_bfloat162*)(olo + di) = __floats2bfloat162_rn(
                    y0 - __bfloat162float(h0), y1 - __bfloat162float(h1));
            }
        }
    }
}

// ---------------------------------------------------------------------------
// V transpose: [b][h][s][hd] -> [b][h][hd][s] (hi and lo)
// ---------------------------------------------------------------------------
__global__ void vtrans_kernel() {
    __shared__ __nv_bfloat16 th[64][65], tl[64][65];
    const int tid = threadIdx.x;
    const int bh = blockIdx.y;
    const int st = blockIdx.x * 64;
    const size_t src0 = ((size_t)bh * PS + st) * PHD;
#pragma unroll
    for (int it = 0; it < 16; it++) {
        const int i = tid + it * 256;
        const int s = i >> 6, hd = i & 63;
        th[hd][s] = g_vhi[src0 + (size_t)s * PHD + hd];
        tl[hd][s] = g_vlo[src0 + (size_t)s * PHD + hd];
    }
    __syncthreads();
    const size_t dst0 = (size_t)bh * PHD * PS + st;
#pragma unroll
    for (int it = 0; it < 16; it++) {
        const int i = tid + it * 256;
        const int hd = i >> 6, s = i & 63;
        g_vthi[dst0 + (size_t)hd * PS + s] = th[hd][s];
        g_vtlo[dst0 + (size_t)hd * PS + s] = tl[hd][s];
    }
}

// ---------------------------------------------------------------------------
// Kernel 2a: scores GEMM (unchanged). 128q x 128k per CTA, single K=64 slab.
// ---------------------------------------------------------------------------
constexpr int SG_SMEM = 4 * 16384;

__global__ __launch_bounds__(256, 2)
void scores_gemm_kernel(float* __restrict__ prob)
{
    extern __shared__ char sm4[];
    char* Qhi_s = sm4;
    char* Qlo_s = sm4 + 16384;
    char* Khi_s = sm4 + 32768;
    char* Klo_s = sm4 + 49152;
    const uint32_t uQhi = smem_to_u32(Qhi_s);
    const uint32_t uQlo = smem_to_u32(Qlo_s);
    const uint32_t uKhi = smem_to_u32(Khi_s);
    const uint32_t uKlo = smem_to_u32(Klo_s);

    const int tid  = threadIdx.x;
    const int warp = tid >> 5;
    const int lane = tid & 31;
    const int wm = warp >> 2;
    const int wn = warp & 3;
    const int bh = blockIdx.z;
    const int q0 = blockIdx.y * 128;
    const int k0 = blockIdx.x * 128;

    const size_t qb = ((size_t)bh * PS + q0) * PHD;
    const size_t kb0 = ((size_t)bh * PS + k0) * PHD;

    load_tile64(g_qhi, qb, Qhi_s, tid);
    load_tile64(g_qlo, qb, Qlo_s, tid);
    load_tile64(g_khi, kb0, Khi_s, tid);
    load_tile64(g_klo, kb0, Klo_s, tid);
    __syncthreads();

    float acc[4][4][4];
#pragma unroll
    for (int i = 0; i < 4; i++)
#pragma unroll
        for (int j = 0; j < 4; j++)
#pragma unroll
            for (int c = 0; c < 4; c++) acc[i][j][c] = 0.0f;

    const int lrow  = lane & 15;
    const int lcolb = (lane >> 4) * 16;

#pragma unroll
    for (int ks = 0; ks < 4; ks++) {
        const int kb = ks * 32 + lcolb;
        uint32_t bhi[2][4], blo[2][4];
#pragma unroll
        for (int nt2 = 0; nt2 < 2; nt2++) {
            const int brow = wn * 32 + nt2 * 16 + lrow;
            ldmx4(bhi[nt2], uKhi + SWZ128(brow * 128 + kb));
            ldmx4(blo[nt2], uKlo + SWZ128(brow * 128 + kb));
        }
#pragma unroll
        for (int mt = 0; mt < 4; mt++) {
            const int arow = wm * 64 + mt * 16 + lrow;
            uint32_t a[4];
            ldmx4(a, uQhi + SWZ128(arow * 128 + kb));       // Qhi
#pragma unroll
            for (int nt2 = 0; nt2 < 2; nt2++)
#pragma unroll
                for (int j = 0; j < 2; j++) {
                    mma16816(acc[mt][nt2 * 2 + j], a, bhi[nt2][j], bhi[nt2][2 + j]);
                    mma16816(acc[mt][nt2 * 2 + j], a, blo[nt2][j], blo[nt2][2 + j]);
                }
            ldmx4(a, uQlo + SWZ128(arow * 128 + kb));       // Qlo
#pragma unroll
            for (int nt2 = 0; nt2 < 2; nt2++)
#pragma unroll
                for (int j = 0; j < 2; j++)
                    mma16816(acc[mt][nt2 * 2 + j], a, bhi[nt2][j], bhi[nt2][2 + j]);
        }
    }

    const int g   = lane >> 2;
    const int tg2 = (lane & 3) * 2;
    const size_t pb = (size_t)bh * PS * PS;
#pragma unroll
    for (int mt = 0; mt < 4; mt++) {
#pragma unroll
        for (int nt = 0; nt < 4; nt++) {
            const int kcol = k0 + wn * 32 + nt * 8 + tg2;
            const int qr = q0 + wm * 64 + mt * 16 + g;
            float2 v0, v1;
            v0.x = acc[mt][nt][0] * 0.125f; v0.y = acc[mt][nt][1] * 0.125f;
            v1.x = acc[mt][nt][2] * 0.125f; v1.y = acc[mt][nt][3] * 0.125f;
            *(float2*)(prob + pb + (size_t)qr * PS + kcol)       = v0;
            *(float2*)(prob + pb + (size_t)(qr + 8) * PS + kcol) = v1;
        }
    }
}

// ---------------------------------------------------------------------------
// Kernel 2b: softmax + combine (unchanged from R12).
// ---------------------------------------------------------------------------
__global__ void softmax_combine_kernel(const float* __restrict__ l1p,
                                       float* __restrict__ prob)
{
    const int lane = threadIdx.x & 31;
    const int warp = threadIdx.x >> 5;
    const int gid = blockIdx.x * 8 + warp;          // bh*1024 + r
    const int bh = gid >> 10, r = gid & 1023;
    const int b = bh / PH;
    const size_t pb = (size_t)gid * PS;
    const size_t mrow = (size_t)b * PS + r;
    const float l1 = *l1p;
    const float w0 = 1.0f - l1;

    const uint32_t myword = g_maskbits[mrow * 32 + lane];
    const int bitbase = (lane & 7) * 4;

    float4 vals[8];
    float mx = -3.0e38f;
#pragma unroll
    for (int j = 0; j < 8; j++) {
        const int col = j * 128 + lane * 4;
        float4 s = *(const float4*)(prob + pb + col);
        const uint32_t w = __shfl_sync(0xffffffffu, myword, j * 4 + (lane >> 3));
        s.x = ((w >> (bitbase + 0)) & 1u) ? -1.0e9f : s.x;
        s.y = ((w >> (bitbase + 1)) & 1u) ? -1.0e9f : s.y;
        s.z = ((w >> (bitbase + 2)) & 1u) ? -1.0e9f : s.z;
        s.w = ((w >> (bitbase + 3)) & 1u) ? -1.0e9f : s.w;
        vals[j] = s;
        mx = fmaxf(mx, fmaxf(fmaxf(s.x, s.y), fmaxf(s.z, s.w)));
    }
#pragma unroll
    for (int o = 16; o; o >>= 1) mx = fmaxf(mx, __shfl_xor_sync(0xffffffffu, mx, o));
    float sum = 0.0f;
#pragma unroll
    for (int j = 0; j < 8; j++) {
        vals[j].x = __expf(vals[j].x - mx);
        vals[j].y = __expf(vals[j].y - mx);
        vals[j].z = __expf(vals[j].z - mx);
        vals[j].w = __expf(vals[j].w - mx);
        sum += vals[j].x + vals[j].y + vals[j].z + vals[j].w;
    }
#pragma unroll
    for (int o = 16; o; o >>= 1) sum += __shfl_xor_sync(0xffffffffu, sum, o);
    const float winv = w0 / sum;
    const float* rp = g_relp + mrow * PS;
#pragma unroll
    for (int j = 0; j < 8; j++) {
        const int col = j * 128 + lane * 4;
        const float4 rv = *(const float4*)(rp + col);
        float4 o;
        o.x = vals[j].x * winv + l1 * rv.x;
        o.y = vals[j].y * winv + l1 * rv.y;
        o.z = vals[j].z * winv + l1 * rv.z;
        o.w = vals[j].w * winv + l1 * rv.w;
        *(float4*)(prob + pb + col) = o;
    }
}

// ---------------------------------------------------------------------------
// Kernel 3: HMMA pv, 2-stage pipeline. Stage p at p*49152:
//   phi(16K) plo(16K) vhi(8K) vlo(8K). Total 96KB, occ 2.
// convert(s+1) + cp.async V(s+1) issue before compute(s).
// ---------------------------------------------------------------------------
constexpr int PV_SMEM = 2 * 49152;

__global__ __launch_bounds__(256, 2)
void pv_mma_kernel(const float* __restrict__ prob, float* __restrict__ outp)
{
    extern __shared__ char sm3[];
    const uint32_t ubase = smem_to_u32(sm3);

    const int tid  = threadIdx.x;
    const int warp = tid >> 5;
    const int lane = tid & 31;
    const int wm = warp >> 1;          // 0..3 (32 q rows)
    const int wn = warp & 1;           // 0..1 (32 hd cols)
    const int bh = blockIdx.y;
    const int b = bh / PH, h = bh % PH;
    const int q0 = blockIdx.x * 128;

    const size_t pbase = ((size_t)bh * PS + q0) * PS;
    const size_t vtb = (size_t)bh * PHD * PS;

    float acc[2][4][4];
#pragma unroll
    for (int i = 0; i < 2; i++)
#pragma unroll
        for (int j = 0; j < 4; j++)
#pragma unroll
            for (int c = 0; c < 4; c++) acc[i][j][c] = 0.0f;

    const int lrow  = lane & 15;
    const int lcolb = (lane >> 4) * 16;

    // convert one prob slab [128 q][64 k] into stage buffers (hi/lo)
    auto convert_slab = [&](int kc0, uint32_t stage_u) {
#pragma unroll
        for (int it = 0; it < 8; it++) {
            const int c = tid + it * 256;
            const int q = c >> 4, k4 = (c & 15) * 4;
            const float4 v = *(const float4*)(prob + pbase + (size_t)q * PS + kc0 + k4);
            const __nv_bfloat16 h0 = __float2bfloat16_rn(v.x);
            const __nv_bfloat16 h1 = __float2bfloat16_rn(v.y);
            const __nv_bfloat16 h2 = __float2bfloat16_rn(v.z);
            const __nv_bfloat16 h3 = __float2bfloat16_rn(v.w);
            __nv_bfloat162 hp01 = __halves2bfloat162(h0, h1);
            __nv_bfloat162 hp23 = __halves2bfloat162(h2, h3);
            __nv_bfloat162 lp01 = __floats2bfloat162_rn(v.x - __bfloat162float(h0),
                                                        v.y - __bfloat162float(h1));
            __nv_bfloat162 lp23 = __floats2bfloat162_rn(v.z - __bfloat162float(h2),
                                                        v.w - __bfloat162float(h3));
            uint2 hv, lv;
            hv.x = *reinterpret_cast<uint32_t*>(&hp01);
            hv.y = *reinterpret_cast<uint32_t*>(&hp23);
            lv.x = *reinterpret_cast<uint32_t*>(&lp01);
            lv.y = *reinterpret_cast<uint32_t*>(&lp23);
            asm volatile("st.shared.v2.b32 [%0], {%1, %2};"
                :: "r"(stage_u + SWZ128(q * 128 + k4 * 2)), "r"(hv.x), "r"(hv.y) : "memory");
            asm volatile("st.shared.v2.b32 [%0], {%1, %2};"
                :: "r"(stage_u + 16384 + SWZ128(q * 128 + k4 * 2)), "r"(lv.x), "r"(lv.y) : "memory");
        }
    };
    // async-load one vT slab [64 hd][64 k] into stage buffers (hi/lo)
    auto loadv_slab = [&](int kc0, uint32_t stage_u) {
#pragma unroll
        for (int it = 0; it < 2; it++) {
            const int c = tid + it * 256;
            const int r = c >> 3, e8 = (c & 7) * 8;
            cp_async16(stage_u + 32768 + SWZ128(r * 128 + e8 * 2),
                       g_vthi + vtb + (size_t)r * PS + kc0 + e8);
            cp_async16(stage_u + 40960 + SWZ128(r * 128 + e8 * 2),
                       g_vtlo + vtb + (size_t)r * PS + kc0 + e8);
        }
    };

    // prologue: stage 0
    convert_slab(0, ubase);
    loadv_slab(0, ubase);
    cp_commit();

    for (int s = 0; s < 16; s++) {
        cp_wait<0>();
        __syncthreads();
        if (s + 1 < 16) {
            const uint32_t nxt = ubase + ((s + 1) & 1) * 49152;
            convert_slab((s + 1) * 64, nxt);
            loadv_slab((s + 1) * 64, nxt);
            cp_commit();
        }
        const uint32_t cur = ubase + (s & 1) * 49152;
        const uint32_t uPhi = cur, uPlo = cur + 16384;
        const uint32_t uVhi = cur + 32768, uVlo = cur + 40960;
#pragma unroll
        for (int ks = 0; ks < 4; ks++) {
            const int kb = ks * 32 + lcolb;
            uint32_t bhi[2][4], blo[2][4];
#pragma unroll
            for (int nt2 = 0; nt2 < 2; nt2++) {
                const int brow = wn * 32 + nt2 * 16 + lrow;
                ldmx4(bhi[nt2], uVhi + SWZ128(brow * 128 + kb));
                ldmx4(blo[nt2], uVlo + SWZ128(brow * 128 + kb));
            }
#pragma unroll
            for (int mt = 0; mt < 2; mt++) {
                const int arow = wm * 32 + mt * 16 + lrow;
                uint32_t a[4];
                ldmx4(a, uPhi + SWZ128(arow * 128 + kb));
#pragma unroll
                for (int nt2 = 0; nt2 < 2; nt2++)
#pragma unroll
                    for (int j = 0; j < 2; j++) {
                        mma16816(acc[mt][nt2 * 2 + j], a, bhi[nt2][j], bhi[nt2][2 + j]);
                        mma16816(acc[mt][nt2 * 2 + j], a, blo[nt2][j], blo[nt2][2 + j]);
                    }
                ldmx4(a, uPlo + SWZ128(arow * 128 + kb));
#pragma unroll
                for (int nt2 = 0; nt2 < 2; nt2++)
#pragma unroll
                    for (int j = 0; j < 2; j++)
                        mma16816(acc[mt][nt2 * 2 + j], a, bhi[nt2][j], bhi[nt2][2 + j]);
            }
        }
        __syncthreads();   // stage (s&1) free before refill at s+2
    }
    // epilogue
    const int g   = lane >> 2;
    const int tg2 = (lane & 3) * 2;
#pragma unroll
    for (int mt = 0; mt < 2; mt++) {
#pragma unroll
        for (int nt = 0; nt < 4; nt++) {
            const int nc = wn * 32 + nt * 8 + tg2;
            const int m = q0 + wm * 32 + mt * 16 + g;
            float2 v0, v1;
            v0.x = acc[mt][nt][0]; v0.y = acc[mt][nt][1];
            v1.x = acc[mt][nt][2]; v1.y = acc[mt][nt][3];
            *(float2*)(outp + ((size_t)b * PS + m) * PD + h * PHD + nc)     = v0;
            *(float2*)(outp + ((size_t)b * PS + m + 8) * PD + h * PHD + nc) = v1;
        }
    }
}

// ---------------------------------------------------------------------------
extern "C" void kernel_launch(void* const* d_in, const int* in_sizes, int n_in,
                              void* d_out, int out_size) {
    const float* query = (const float*)d_in[0];
    const float* key   = (const float*)d_in[1];
    const float* value = (const float*)d_in[2];
    const float* rel   = (const float*)d_in[3];
    const void*  mask  = d_in[4];
    const float* l1    = (const float*)d_in[5];
    const float* Wq    = (const float*)d_in[6];
    const float* bq    = (const float*)d_in[7];
    const float* Wk    = (const float*)d_in[8];
    const float* bk    = (const float*)d_in[9];
    const float* Wv    = (const float*)d_in[10];
    const float* bv    = (const float*)d_in[11];

    float* outp = (float*)d_out;
    float* prob = outp + OUT_ELEMS;

    detect_mask_kernel<<<1, 256>>>(mask);

    conv_x_kernel<<<dim3((unsigned)(XE / 512), 3), 256>>>(query, key, value);
    conv_w_kernel<<<dim3((unsigned)(WE / 512), 3), 256>>>(Wq, Wk, Wv);
    relp_kernel<<<1024, 256>>>(rel, mask);

    cudaFuncSetAttribute(proj_mma_kernel,
                         cudaFuncAttributeMaxDynamicSharedMemorySize, PROJ_SMEM);
    dim3 g1(PD / 128, (PB * PS) / 128, 3);     // (6, 64, 3)
    proj_mma_kernel<<<g1, 256, PROJ_SMEM>>>(bq, bk, bv);

    vtrans_kernel<<<dim3(16, PB * PH), 256>>>();

    cudaFuncSetAttribute(scores_gemm_kernel,
                         cudaFuncAttributeMaxDynamicSharedMemorySize, SG_SMEM);
    dim3 g2(PS / 128, PS / 128, PB * PH);      // (8, 8, 96)
    scores_gemm_kernel<<<g2, 256, SG_SMEM>>>(prob);

    softmax_combine_kernel<<<(PB * PH * PS) / 8, 256>>>(l1, prob);

    cudaFuncSetAttribute(pv_mma_kernel,
                         cudaFuncAttributeMaxDynamicSharedMemorySize, PV_SMEM);
    dim3 g3(PS / 128, PB * PH);                // (8, 96)
    pv_mma_kernel<<<g3, 256, PV_SMEM>>>(prob, outp);
}